// round 1
// baseline (speedup 1.0000x reference)
#include <cuda_runtime.h>
#include <math.h>
#include <stdint.h>

#define NPIX 262144   // 512*512
#define NIMG 24       // 8 batch * 3 channels

// ---------------- scratch (device globals: allowed; no allocation) ----------
static __device__ float2 g_nfq[NIMG * NPIX];     // noisy spectrum (unshifted), later reused for Dm
static __device__ float2 g_cfq[NIMG * NPIX];     // clean spectrum (unshifted)
static __device__ float  g_fin[8 * 12 * NPIX];   // filter_input (B,12,512,512)
static __device__ float  g_y1 [8 * 16 * NPIX];
static __device__ float  g_p1 [8 * 16 * 65536];
static __device__ float  g_y2 [8 * 32 * 65536];
static __device__ float  g_p2 [8 * 32 * 16384];
static __device__ float  g_y3 [8 * 64 * 16384];
static __device__ float  g_feat[8 * 64];
static __device__ float  g_h  [8 * 256];
static __device__ float  g_vset[8 * 100];
static __device__ float2 g_tw [256];             // W_512^k = exp(-2*pi*i*k/512)

// ---------------- twiddles ---------------------------------------------------
__global__ void init_tw_kernel() {
    int k = threadIdx.x;
    if (k < 256) {
        double s, c;
        sincospi(-(double)k / 256.0, &s, &c);   // theta = -2*pi*k/512
        g_tw[k] = make_float2((float)c, (float)s);
    }
}

// ---------------- shared-memory radix-2 512-pt FFT (DIT, bit-reversed input) -
// sd holds nff independent 512-point sequences (stride 512). Caller must
// __syncthreads() after loading sd. Each stage ends with a sync.
__device__ __forceinline__ void fft_stages(float2* sd, const float2* tw,
                                           int tid, int nff, int sign) {
    const int total = nff * 256;
    for (int s = 0; s < 9; s++) {
        const int half = 1 << s;
        for (int g = tid; g < total; g += 512) {
            int row  = g >> 8;
            int j    = g & 255;
            int k    = j & (half - 1);
            int base = row * 512 + ((j >> s) << (s + 1)) + k;
            float2 a = sd[base];
            float2 b = sd[base + half];
            float2 w = tw[k << (8 - s)];
            float wy = (sign < 0) ? w.y : -w.y;
            float bwx = b.x * w.x - b.y * wy;
            float bwy = b.x * wy + b.y * w.x;
            sd[base]        = make_float2(a.x + bwx, a.y + bwy);
            sd[base + half] = make_float2(a.x - bwx, a.y - bwy);
        }
        __syncthreads();
    }
}

// ---------------- forward FFT: rows (real input) -----------------------------
__global__ void __launch_bounds__(512)
fwd_rows_kernel(const float* __restrict__ noisy, const float* __restrict__ clean) {
    __shared__ float2 sd[8 * 512];
    __shared__ float2 tw[256];
    int tid = threadIdx.x;
    if (tid < 256) tw[tid] = g_tw[tid];
    int img = blockIdx.y;            // 0..47 (<24: noisy, else clean)
    int r0  = blockIdx.x * 8;
    const float* src = (img < 24) ? (noisy + (size_t)img * NPIX)
                                  : (clean + (size_t)(img - 24) * NPIX);
    float2* dst = ((img < 24) ? g_nfq : g_cfq) + (size_t)(img % 24) * NPIX;

    for (int e = tid; e < 8 * 512; e += 512) {
        int row = e >> 9, i = e & 511;
        float v = src[(size_t)(r0 + row) * 512 + i];
        sd[row * 512 + (__brev((unsigned)i) >> 23)] = make_float2(v, 0.f);
    }
    __syncthreads();
    fft_stages(sd, tw, tid, 8, -1);
    for (int e = tid; e < 8 * 512; e += 512) {
        int row = e >> 9, i = e & 511;
        dst[(size_t)(r0 + row) * 512 + i] = sd[row * 512 + i];
    }
}

// ---------------- forward FFT: columns + log-magnitude epilogue --------------
__global__ void __launch_bounds__(512)
fwd_cols_kernel() {
    __shared__ float2 sd[8 * 512];
    __shared__ float2 tw[256];
    int tid = threadIdx.x;
    if (tid < 256) tw[tid] = g_tw[tid];
    int img = blockIdx.y;            // 0..47
    int c0  = blockIdx.x * 8;
    int imgl = img % 24;
    float2* buf = ((img < 24) ? g_nfq : g_cfq) + (size_t)imgl * NPIX;

    for (int e = tid; e < 8 * 512; e += 512) {
        int c = e & 7, r = e >> 3;
        float2 v = buf[(size_t)r * 512 + c0 + c];
        sd[c * 512 + (__brev((unsigned)r) >> 23)] = v;
    }
    __syncthreads();
    fft_stages(sd, tw, tid, 8, -1);

    int b = imgl / 3, ch = imgl % 3;
    int chbase = (img < 24) ? 3 : 9;
    float* fin = g_fin + (size_t)(b * 12 + chbase + ch) * NPIX;
    for (int e = tid; e < 8 * 512; e += 512) {
        int c = e & 7, r = e >> 3;
        float2 v = sd[c * 512 + r];
        buf[(size_t)r * 512 + c0 + c] = v;
        int ys = (r + 256) & 511, xs = (c0 + c + 256) & 511;
        fin[(size_t)ys * 512 + xs] = log10f(sqrtf(v.x * v.x + v.y * v.y) + 1.f);
    }
}

// ---------------- copy spatial channels into filter_input --------------------
__global__ void copy_spatial_kernel(const float* __restrict__ noisy,
                                    const float* __restrict__ clean) {
    int idx = blockIdx.x * blockDim.x + threadIdx.x;
    if (idx >= 8 * 3 * NPIX) return;
    int b = idx / (3 * NPIX);
    int c = (idx / NPIX) % 3;
    int pix = idx & (NPIX - 1);
    g_fin[(size_t)(b * 12 + c) * NPIX + pix]     = noisy[idx];
    g_fin[(size_t)(b * 12 + 6 + c) * NPIX + pix] = clean[idx];
}

// ---------------- direct 3x3 conv + bias + relu ------------------------------
template <int CIN, int CINBLK, int COUTG>
__global__ void __launch_bounds__(128)
conv3x3_relu_kernel(const float* __restrict__ in, const float* __restrict__ wgt,
                    const float* __restrict__ bias, float* __restrict__ out,
                    int H, int W, int COUT) {
    __shared__ float sIn[CINBLK][18][34];
    __shared__ float sW[COUTG][CINBLK][9];
    const int groups = COUT / COUTG;
    int og = blockIdx.z % groups;
    int b  = blockIdx.z / groups;
    int x0 = blockIdx.x * 32;
    int y0 = blockIdx.y * 16;
    int tid = threadIdx.x;
    int tx  = tid & 31;
    int ty0 = (tid >> 5) * 4;

    float acc[COUTG][4];
#pragma unroll
    for (int o = 0; o < COUTG; o++)
#pragma unroll
        for (int p = 0; p < 4; p++) acc[o][p] = 0.f;

    for (int cb = 0; cb < CIN; cb += CINBLK) {
        __syncthreads();
        for (int e = tid; e < CINBLK * 18 * 34; e += 128) {
            int ic = e / (18 * 34);
            int r  = (e / 34) % 18;
            int cc = e % 34;
            int gy = y0 + r - 1, gx = x0 + cc - 1;
            float v = 0.f;
            if (gy >= 0 && gy < H && gx >= 0 && gx < W)
                v = in[((size_t)(b * CIN + cb + ic) * H + gy) * W + gx];
            sIn[ic][r][cc] = v;
        }
        for (int e = tid; e < COUTG * CINBLK * 9; e += 128) {
            int o = e / (CINBLK * 9);
            int rem = e % (CINBLK * 9);
            sW[o][rem / 9][rem % 9] =
                wgt[((og * COUTG + o) * CIN + cb + rem / 9) * 9 + rem % 9];
        }
        __syncthreads();
        for (int ic = 0; ic < CINBLK; ic++) {
#pragma unroll
            for (int ky = 0; ky < 3; ky++)
#pragma unroll
            for (int kx = 0; kx < 3; kx++) {
                float v[4];
#pragma unroll
                for (int p = 0; p < 4; p++) v[p] = sIn[ic][ty0 + p + ky][tx + kx];
#pragma unroll
                for (int o = 0; o < COUTG; o++) {
                    float wv = sW[o][ic][ky * 3 + kx];
#pragma unroll
                    for (int p = 0; p < 4; p++)
                        acc[o][p] = fmaf(wv, v[p], acc[o][p]);
                }
            }
        }
    }
#pragma unroll
    for (int o = 0; o < COUTG; o++) {
        float bv = bias[og * COUTG + o];
#pragma unroll
        for (int p = 0; p < 4; p++) {
            int oy = y0 + ty0 + p;
            out[((size_t)(b * COUT + og * COUTG + o) * H + oy) * W + x0 + tx] =
                fmaxf(acc[o][p] + bv, 0.f);
        }
    }
}

// ---------------- 2x2 average pool -------------------------------------------
__global__ void pool2x2_kernel(const float* __restrict__ in, float* __restrict__ out,
                               int n, int Ho, int Wo) {
    int idx = blockIdx.x * blockDim.x + threadIdx.x;
    if (idx >= n) return;
    int x = idx % Wo;
    int y = (idx / Wo) % Ho;
    int c = idx / (Wo * Ho);
    const float* p = in + ((size_t)c * Ho * 2 + y * 2) * (Wo * 2) + x * 2;
    out[idx] = 0.25f * (p[0] + p[1] + p[Wo * 2] + p[Wo * 2 + 1]);
}

// ---------------- global mean over 128x128 -----------------------------------
__global__ void __launch_bounds__(256)
reduce_mean_kernel(const float* __restrict__ y3) {
    __shared__ float red[256];
    int bc = blockIdx.x;       // 0..511 (b*64+c)
    int t  = threadIdx.x;
    const float* p = y3 + (size_t)bc * 16384;
    float s = 0.f;
    for (int i = t; i < 16384; i += 256) s += p[i];
    red[t] = s;
    __syncthreads();
    for (int off = 128; off; off >>= 1) {
        if (t < off) red[t] += red[t + off];
        __syncthreads();
    }
    if (t == 0) g_feat[bc] = red[0] * (1.f / 16384.f);
}

// ---------------- fc1 (no activation) ----------------------------------------
__global__ void __launch_bounds__(256)
fc1_kernel(const float* __restrict__ w, const float* __restrict__ bias) {
    __shared__ float sf[64];
    int b = blockIdx.x, t = threadIdx.x;
    if (t < 64) sf[t] = g_feat[b * 64 + t];
    __syncthreads();
    float s = 0.f;
    const float* wr = w + (size_t)t * 64;
#pragma unroll
    for (int i = 0; i < 64; i++) s = fmaf(wr[i], sf[i], s);
    g_h[b * 256 + t] = s + bias[t];
}

// ---------------- fc2 row + softmax*temp + radius-weighted sum ---------------
__global__ void __launch_bounds__(128)
head_kernel(const float* __restrict__ w, const float* __restrict__ bias) {
    __shared__ float sh[256];
    __shared__ float red[128];
    int j = blockIdx.x;   // 0..99 (row of reshape)
    int b = blockIdx.y;   // 0..7
    int t = threadIdx.x;
    for (int i = t; i < 256; i += 128) sh[i] = g_h[b * 256 + i];
    __syncthreads();
    float z = -3.4e38f;
    if (t < 100) {
        const float* wr = w + (size_t)(j * 100 + t) * 256;
        float s = 0.f;
        for (int i = 0; i < 256; i++) s = fmaf(wr[i], sh[i], s);
        z = (s + bias[j * 100 + t]) * 0.1f;   // TEMPERATURE
    }
    red[t] = z;
    __syncthreads();
    for (int off = 64; off; off >>= 1) {
        if (t < off) red[t] = fmaxf(red[t], red[t + off]);
        __syncthreads();
    }
    float m = red[0];
    __syncthreads();
    float p = (t < 100) ? expf(z - m) : 0.f;
    red[t] = p;
    __syncthreads();
    for (int off = 64; off; off >>= 1) {
        if (t < off) red[t] += red[t + off];
        __syncthreads();
    }
    float S = red[0];
    __syncthreads();
    float rf = ((float)t + 1.0f) * 0.01f;
    red[t] = p * rf;
    __syncthreads();
    for (int off = 64; off; off >>= 1) {
        if (t < off) red[t] += red[t + off];
        __syncthreads();
    }
    if (t == 0) g_vset[b * 100 + j] = red[0] / S;
}

// ---------------- radial mask (searchsorted right) ---------------------------
__global__ void mask_kernel(float* __restrict__ outMask) {
    int idx = blockIdx.x * blockDim.x + threadIdx.x;
    if (idx >= 8 * NPIX) return;
    int b = idx >> 18;
    int pix = idx & (NPIX - 1);
    int y = pix >> 9, x = pix & 511;
    float dy = (float)y - 256.f, dx = (float)x - 256.f;
    float dist = sqrtf(dy * dy + dx * dx);
    const float MAXR = 362.03867196751236f;   // sqrt(512^2+512^2)/2 as f32
    int lo = 0, hi = 100;
    while (lo < hi) {
        int mid = (lo + hi) >> 1;
        float r = MAXR * (((float)(mid + 1)) * 0.01f);
        if (r <= dist) lo = mid + 1; else hi = mid;
    }
    outMask[idx] = (lo < 100) ? g_vset[b * 100 + lo] : 0.f;
}

// ---------------- Dm = m_shift * (N - C)  (overwrite g_nfq) ------------------
__global__ void combine_kernel(const float* __restrict__ maskp) {
    int idx = blockIdx.x * blockDim.x + threadIdx.x;
    if (idx >= NIMG * NPIX) return;
    int img = idx >> 18;
    int pix = idx & (NPIX - 1);
    int u = pix >> 9, v = pix & 511;
    int b = img / 3;
    float m = maskp[(size_t)b * NPIX + (size_t)(((u + 256) & 511) << 9) + ((v + 256) & 511)];
    float2 n = g_nfq[idx];
    float2 c = g_cfq[idx];
    g_nfq[idx] = make_float2(m * (n.x - c.x), m * (n.y - c.y));
}

// ---------------- inverse FFT rows -------------------------------------------
__global__ void __launch_bounds__(512)
inv_rows_kernel() {
    __shared__ float2 sd[8 * 512];
    __shared__ float2 tw[256];
    int tid = threadIdx.x;
    if (tid < 256) tw[tid] = g_tw[tid];
    int img = blockIdx.y;     // 0..23
    int r0  = blockIdx.x * 8;
    float2* buf = g_nfq + (size_t)img * NPIX;
    for (int e = tid; e < 8 * 512; e += 512) {
        int row = e >> 9, i = e & 511;
        sd[row * 512 + (__brev((unsigned)i) >> 23)] = buf[(size_t)(r0 + row) * 512 + i];
    }
    __syncthreads();
    fft_stages(sd, tw, tid, 8, +1);
    for (int e = tid; e < 8 * 512; e += 512) {
        int row = e >> 9, i = e & 511;
        buf[(size_t)(r0 + row) * 512 + i] = sd[row * 512 + i];
    }
}

// ---------------- inverse FFT cols + hard/easy epilogue ----------------------
__global__ void __launch_bounds__(512)
inv_cols_kernel(const float* __restrict__ clean, const float* __restrict__ noisy,
                float* __restrict__ hard, float* __restrict__ easy) {
    __shared__ float2 sd[8 * 512];
    __shared__ float2 tw[256];
    int tid = threadIdx.x;
    if (tid < 256) tw[tid] = g_tw[tid];
    int img = blockIdx.y;     // 0..23
    int c0  = blockIdx.x * 8;
    float2* buf = g_nfq + (size_t)img * NPIX;
    for (int e = tid; e < 8 * 512; e += 512) {
        int c = e & 7, r = e >> 3;
        float2 v = buf[(size_t)r * 512 + c0 + c];
        sd[c * 512 + (__brev((unsigned)r) >> 23)] = v;
    }
    __syncthreads();
    fft_stages(sd, tw, tid, 8, +1);
    const float scale = 1.f / 262144.f;
    for (int e = tid; e < 8 * 512; e += 512) {
        int c = e & 7, r = e >> 3;
        float re = sd[c * 512 + r].x * scale;
        size_t gi = (size_t)img * NPIX + (size_t)r * 512 + c0 + c;
        hard[gi] = clean[gi] + re;
        easy[gi] = noisy[gi] - re;
    }
}

// ---------------- launch ------------------------------------------------------
extern "C" void kernel_launch(void* const* d_in, const int* in_sizes, int n_in,
                              void* d_out, int out_size) {
    const float* clean = (const float*)d_in[0];
    const float* noisy = (const float*)d_in[1];
    const float* c1w = (const float*)d_in[2];
    const float* c1b = (const float*)d_in[3];
    const float* c2w = (const float*)d_in[4];
    const float* c2b = (const float*)d_in[5];
    const float* c3w = (const float*)d_in[6];
    const float* c3b = (const float*)d_in[7];
    const float* f1w = (const float*)d_in[8];
    const float* f1b = (const float*)d_in[9];
    const float* f2w = (const float*)d_in[10];
    const float* f2b = (const float*)d_in[11];

    float* hard  = (float*)d_out;
    float* easy  = hard + 6291456;
    float* maskp = easy + 6291456;

    float *p_fin, *p_y1, *p_p1, *p_y2, *p_p2, *p_y3;
    cudaGetSymbolAddress((void**)&p_fin, g_fin);
    cudaGetSymbolAddress((void**)&p_y1, g_y1);
    cudaGetSymbolAddress((void**)&p_p1, g_p1);
    cudaGetSymbolAddress((void**)&p_y2, g_y2);
    cudaGetSymbolAddress((void**)&p_p2, g_p2);
    cudaGetSymbolAddress((void**)&p_y3, g_y3);

    init_tw_kernel<<<1, 256>>>();

    fwd_rows_kernel<<<dim3(64, 48), 512>>>(noisy, clean);
    fwd_cols_kernel<<<dim3(64, 48), 512>>>();
    copy_spatial_kernel<<<(8 * 3 * NPIX + 255) / 256, 256>>>(noisy, clean);

    conv3x3_relu_kernel<12, 12, 16><<<dim3(16, 32, 8), 128>>>(p_fin, c1w, c1b, p_y1, 512, 512, 16);
    pool2x2_kernel<<<(8 * 16 * 65536 + 255) / 256, 256>>>(p_y1, p_p1, 8 * 16 * 65536, 256, 256);
    conv3x3_relu_kernel<16, 16, 16><<<dim3(8, 16, 16), 128>>>(p_p1, c2w, c2b, p_y2, 256, 256, 32);
    pool2x2_kernel<<<(8 * 32 * 16384 + 255) / 256, 256>>>(p_y2, p_p2, 8 * 32 * 16384, 128, 128);
    conv3x3_relu_kernel<32, 16, 16><<<dim3(4, 8, 32), 128>>>(p_p2, c3w, c3b, p_y3, 128, 128, 64);
    reduce_mean_kernel<<<512, 256>>>(p_y3);
    fc1_kernel<<<8, 256>>>(f1w, f1b);
    head_kernel<<<dim3(100, 8), 128>>>(f2w, f2b);

    mask_kernel<<<(8 * NPIX + 255) / 256, 256>>>(maskp);
    combine_kernel<<<(NIMG * NPIX + 255) / 256, 256>>>(maskp);
    inv_rows_kernel<<<dim3(64, 24), 512>>>();
    inv_cols_kernel<<<dim3(64, 24), 512>>>(clean, noisy, hard, easy);
}

// round 2
// speedup vs baseline: 1.1120x; 1.1120x over previous
#include <cuda_runtime.h>
#include <math.h>
#include <stdint.h>

#define NPIX 262144   // 512*512
#define NIMG 24       // 8 batch * 3 channels

// ---------------- scratch (device globals) -----------------------------------
static __device__ float2 g_nfq[NIMG * NPIX];     // noisy spectrum (natural order)
static __device__ float2 g_cfq[NIMG * NPIX];     // clean spectrum
static __device__ float  g_fin[8 * 6 * NPIX];    // fq log-mag channels (B,6,512,512)
static __device__ float  g_p1 [8 * 16 * 65536];  // pooled conv1 out (256^2)
static __device__ float  g_p2 [8 * 32 * 16384];  // pooled conv2 out (128^2)
static __device__ float  g_y3 [8 * 64 * 16384];  // conv3 out (128^2)
static __device__ float  g_feat[8 * 64];
static __device__ float  g_h  [8 * 256];
static __device__ float  g_vset[8 * 100];
static __device__ float2 g_tw [512];             // W_512^k = exp(-2*pi*i*k/512)

// ---------------- twiddles ---------------------------------------------------
__global__ void init_tw_kernel() {
    int k = threadIdx.x;
    if (k < 512) {
        double s, c;
        sincospi(-(double)k / 256.0, &s, &c);
        g_tw[k] = make_float2((float)c, (float)s);
    }
}

// ---------------- complex helpers --------------------------------------------
__device__ __forceinline__ float2 cadd(float2 a, float2 b){ return make_float2(a.x+b.x, a.y+b.y); }
__device__ __forceinline__ float2 csub(float2 a, float2 b){ return make_float2(a.x-b.x, a.y-b.y); }
// w = exp(-i theta) table entry. INV=0: a*w ; INV=1: a*conj(w)
template<int INV>
__device__ __forceinline__ float2 ctw(float2 a, float2 w) {
    if (!INV) return make_float2(a.x*w.x - a.y*w.y, a.x*w.y + a.y*w.x);
    else      return make_float2(a.x*w.x + a.y*w.y, a.y*w.x - a.x*w.y);
}

// ---------------- 8-point DFT (natural in, natural out) ----------------------
template<int INV>
__device__ __forceinline__ void dft8(float2* a) {
    const float C = 0.70710678118654752f;
    float2 b0 = cadd(a[0], a[4]), t4 = csub(a[0], a[4]);
    float2 b1 = cadd(a[1], a[5]), t5 = csub(a[1], a[5]);
    float2 b2 = cadd(a[2], a[6]), t6 = csub(a[2], a[6]);
    float2 b3 = cadd(a[3], a[7]), t7 = csub(a[3], a[7]);
    float2 b5, b6, b7;
    if (!INV) {
        b5 = make_float2(C*(t5.x + t5.y), C*(t5.y - t5.x));   // * (c,-c)
        b6 = make_float2(t6.y, -t6.x);                        // * -i
        b7 = make_float2(C*(t7.y - t7.x), -C*(t7.x + t7.y));  // * (-c,-c)
    } else {
        b5 = make_float2(C*(t5.x - t5.y), C*(t5.y + t5.x));   // * (c,c)
        b6 = make_float2(-t6.y, t6.x);                        // * +i
        b7 = make_float2(-C*(t7.x + t7.y), C*(t7.x - t7.y));  // * (-c,c)
    }
    float2 c0 = cadd(b0, b2), c2 = csub(b0, b2);
    float2 c1 = cadd(b1, b3), t3 = csub(b1, b3);
    float2 c4 = cadd(t4, b6), c6 = csub(t4, b6);
    float2 c5 = cadd(b5, b7), t7b = csub(b5, b7);
    float2 c3 = (!INV) ? make_float2(t3.y, -t3.x)  : make_float2(-t3.y, t3.x);
    float2 c7 = (!INV) ? make_float2(t7b.y, -t7b.x): make_float2(-t7b.y, t7b.x);
    a[0] = cadd(c0, c1); a[4] = csub(c0, c1);
    a[2] = cadd(c2, c3); a[6] = csub(c2, c3);
    a[1] = cadd(c4, c5); a[5] = csub(c4, c5);
    a[3] = cadd(c6, c7); a[7] = csub(c6, c7);
}

#define FPAD(p) ((p) + ((p) >> 3))   // 512 -> 576 padded slots
__device__ __forceinline__ int drev(int i) {   // base-8 digit reverse, 3 digits
    return ((i & 7) << 6) | (i & 56) | (i >> 6);
}

// ---------------- radix-8 DIT, 8 sequences per block, 512 threads ------------
// Input must be loaded at digit-reversed padded positions; output natural.
template<int INV>
__device__ __forceinline__ void fft512_stages(float2 (*sd)[576], const float2* stw) {
    int tid = threadIdx.x;
    float2* s = sd[tid >> 6];
    int t = tid & 63;
    // stage L=1 (no twiddles)
    {
        float2 a[8];
#pragma unroll
        for (int j = 0; j < 8; j++) { int p = 8*t + j; a[j] = s[FPAD(p)]; }
        dft8<INV>(a);
#pragma unroll
        for (int m = 0; m < 8; m++) { int p = 8*t + m; s[FPAD(p)] = a[m]; }
    }
    __syncthreads();
    // stage L=8: twiddle W_64^{jk} = tw[8jk]
    {
        int k = t & 7, base = ((t >> 3) << 6) + k;
        float2 a[8];
        a[0] = s[FPAD(base)];
#pragma unroll
        for (int j = 1; j < 8; j++) {
            int p = base + 8*j;
            a[j] = ctw<INV>(s[FPAD(p)], stw[8*j*k]);
        }
        dft8<INV>(a);
#pragma unroll
        for (int m = 0; m < 8; m++) { int p = base + 8*m; s[FPAD(p)] = a[m]; }
    }
    __syncthreads();
    // stage L=64: twiddle W_512^{jk} = tw[jk]
    {
        float2 a[8];
        a[0] = s[FPAD(t)];
#pragma unroll
        for (int j = 1; j < 8; j++) {
            int p = t + 64*j;
            a[j] = ctw<INV>(s[FPAD(p)], stw[j*t]);
        }
        dft8<INV>(a);
#pragma unroll
        for (int m = 0; m < 8; m++) { int p = t + 64*m; s[FPAD(p)] = a[m]; }
    }
    __syncthreads();
}

// ---------------- forward FFT: rows (real input) -----------------------------
__global__ void __launch_bounds__(512)
fwd_rows_kernel(const float* __restrict__ noisy, const float* __restrict__ clean) {
    __shared__ float2 sd[8][576];
    __shared__ float2 stw[512];
    int tid = threadIdx.x;
    stw[tid] = g_tw[tid];
    int img = blockIdx.y;            // 0..47
    int r0  = blockIdx.x * 8;
    const float* src = (img < 24) ? (noisy + (size_t)img * NPIX)
                                  : (clean + (size_t)(img - 24) * NPIX);
    float2* dst = ((img < 24) ? g_nfq : g_cfq) + (size_t)(img % 24) * NPIX;

#pragma unroll
    for (int row = 0; row < 8; row++) {
        float v = src[(size_t)(r0 + row) * 512 + tid];
        int p = drev(tid);
        sd[row][FPAD(p)] = make_float2(v, 0.f);
    }
    __syncthreads();
    fft512_stages<0>(sd, stw);
#pragma unroll
    for (int row = 0; row < 8; row++)
        dst[(size_t)(r0 + row) * 512 + tid] = sd[row][FPAD(tid)];
}

// ---------------- forward FFT: columns + log-magnitude epilogue --------------
__global__ void __launch_bounds__(512)
fwd_cols_kernel() {
    __shared__ float2 sd[8][576];
    __shared__ float2 stw[512];
    int tid = threadIdx.x;
    stw[tid] = g_tw[tid];
    int img = blockIdx.y;            // 0..47
    int c0  = blockIdx.x * 8;
    int imgl = img % 24;
    float2* buf = ((img < 24) ? g_nfq : g_cfq) + (size_t)imgl * NPIX;

    int c = tid & 7;
#pragma unroll
    for (int it = 0; it < 8; it++) {
        int r = it * 64 + (tid >> 3);
        float2 v = buf[(size_t)r * 512 + c0 + c];
        int p = drev(r);
        sd[c][FPAD(p)] = v;
    }
    __syncthreads();
    fft512_stages<0>(sd, stw);

    int b = imgl / 3, ch = imgl % 3;
    int chbase = (img < 24) ? 0 : 3;
    float* fin = g_fin + (size_t)(b * 6 + chbase + ch) * NPIX;
#pragma unroll
    for (int it = 0; it < 8; it++) {
        int r = it * 64 + (tid >> 3);
        float2 v = sd[c][FPAD(r)];
        buf[(size_t)r * 512 + c0 + c] = v;
        int ys = (r + 256) & 511, xs = (c0 + c + 256) & 511;
        fin[(size_t)ys * 512 + xs] = log10f(sqrtf(v.x * v.x + v.y * v.y) + 1.f);
    }
}

// ---------------- packed f32x2 helpers ---------------------------------------
__device__ __forceinline__ unsigned long long pk2(float lo, float hi) {
    unsigned long long r;
    asm("mov.b64 %0, {%1,%2};" : "=l"(r) : "f"(lo), "f"(hi));
    return r;
}
__device__ __forceinline__ void upk2(unsigned long long v, float& lo, float& hi) {
    asm("mov.b64 {%0,%1}, %2;" : "=f"(lo), "=f"(hi) : "l"(v));
}
#define FMA2(acc, a, b) asm("fma.rn.f32x2 %0, %1, %2, %0;" : "+l"(acc) : "l"(a), "l"(b))

// ---------------- 3x3 conv + bias + relu (+optional fused 2x2 avgpool) -------
// block = 128 threads; output tile 32x32; per thread: 2x * 4y pixels, 8 couts
template<int CIN, int CINBLK, bool GATHER, bool POOL>
__global__ void __launch_bounds__(128)
conv3x3_kernel(const float* __restrict__ in,
               const float* __restrict__ noisy, const float* __restrict__ clean,
               const float* __restrict__ fin,
               const float* __restrict__ wgt, const float* __restrict__ bias,
               float* __restrict__ out, int H, int W, int COUT) {
    __shared__ __align__(16) float sIn[CINBLK][34][36];
    __shared__ unsigned long long sWp[8][CINBLK][9];
    const int groups = COUT >> 3;
    int og = blockIdx.z % groups;
    int b  = blockIdx.z / groups;
    int x0 = blockIdx.x * 32, y0 = blockIdx.y * 32;
    int tid = threadIdx.x;
    int tx  = tid & 15;        // x pair index: out x = x0 + 2tx + {0,1}
    int tyq = tid >> 4;        // out y = y0 + tyq*4 + {0..3}

    unsigned long long acc[8][4];
#pragma unroll
    for (int o = 0; o < 8; o++) {
        float bv = bias[og * 8 + o];
        unsigned long long bb = pk2(bv, bv);
#pragma unroll
        for (int p = 0; p < 4; p++) acc[o][p] = bb;
    }

    for (int cb = 0; cb < CIN; cb += CINBLK) {
        __syncthreads();
        for (int e = tid; e < CINBLK * 34 * 34; e += 128) {
            int ic = e / (34 * 34);
            int r  = (e / 34) % 34;
            int cc = e % 34;
            int gy = y0 + r - 1, gx = x0 + cc - 1;
            float v = 0.f;
            if ((unsigned)gy < (unsigned)H && (unsigned)gx < (unsigned)W) {
                int cin = cb + ic;
                if (GATHER) {
                    int grp = cin / 3, sub = cin % 3;
                    const float* src =
                        (grp == 0) ? noisy + (size_t)(b * 3 + sub) * NPIX :
                        (grp == 1) ? fin   + (size_t)(b * 6 + sub) * NPIX :
                        (grp == 2) ? clean + (size_t)(b * 3 + sub) * NPIX :
                                     fin   + (size_t)(b * 6 + 3 + sub) * NPIX;
                    v = src[(size_t)gy * 512 + gx];
                } else {
                    v = in[((size_t)(b * CIN + cin) * H + gy) * W + gx];
                }
            }
            sIn[ic][r][cc] = v;
        }
        for (int e = tid; e < 8 * CINBLK * 9; e += 128) {
            int o = e / (CINBLK * 9);
            int rem = e % (CINBLK * 9);
            float wv = wgt[((og * 8 + o) * CIN + cb + rem / 9) * 9 + rem % 9];
            sWp[o][rem / 9][rem % 9] = pk2(wv, wv);
        }
        __syncthreads();
        for (int ic = 0; ic < CINBLK; ic++) {
#pragma unroll
            for (int ky = 0; ky < 3; ky++) {
                unsigned long long pr[4][3];
#pragma unroll
                for (int p = 0; p < 4; p++) {
                    const float* rp = &sIn[ic][tyq * 4 + ky + p][2 * tx];
                    float2 va = *(const float2*)(rp);
                    float2 vb = *(const float2*)(rp + 2);
                    pr[p][0] = pk2(va.x, va.y);
                    pr[p][1] = pk2(va.y, vb.x);
                    pr[p][2] = pk2(vb.x, vb.y);
                }
#pragma unroll
                for (int kx = 0; kx < 3; kx++) {
#pragma unroll
                    for (int o = 0; o < 8; o++) {
                        unsigned long long ww = sWp[o][ic][ky * 3 + kx];
#pragma unroll
                        for (int p = 0; p < 4; p++) FMA2(acc[o][p], pr[p][kx], ww);
                    }
                }
            }
        }
    }

    if (POOL) {
        int Ho = H >> 1, Wo = W >> 1;
#pragma unroll
        for (int o = 0; o < 8; o++) {
#pragma unroll
            for (int q = 0; q < 2; q++) {
                float a0, a1, b0v, b1v;
                upk2(acc[o][2 * q + 0], a0, a1);
                upk2(acc[o][2 * q + 1], b0v, b1v);
                float pv = 0.25f * (fmaxf(a0, 0.f) + fmaxf(a1, 0.f) +
                                    fmaxf(b0v, 0.f) + fmaxf(b1v, 0.f));
                int oy = (y0 >> 1) + tyq * 2 + q;
                int ox = (x0 >> 1) + tx;
                out[((size_t)(b * COUT + og * 8 + o) * Ho + oy) * Wo + ox] = pv;
            }
        }
    } else {
#pragma unroll
        for (int o = 0; o < 8; o++) {
#pragma unroll
            for (int p = 0; p < 4; p++) {
                float v0, v1;
                upk2(acc[o][p], v0, v1);
                float2 rv = make_float2(fmaxf(v0, 0.f), fmaxf(v1, 0.f));
                int oy = y0 + tyq * 4 + p;
                *(float2*)&out[((size_t)(b * COUT + og * 8 + o) * H + oy) * W + x0 + 2 * tx] = rv;
            }
        }
    }
}

// ---------------- global mean over 128x128 -----------------------------------
__global__ void __launch_bounds__(256)
reduce_mean_kernel(const float* __restrict__ y3) {
    __shared__ float red[256];
    int bc = blockIdx.x;
    int t  = threadIdx.x;
    const float* p = y3 + (size_t)bc * 16384;
    float s = 0.f;
    for (int i = t; i < 16384; i += 256) s += p[i];
    red[t] = s;
    __syncthreads();
    for (int off = 128; off; off >>= 1) {
        if (t < off) red[t] += red[t + off];
        __syncthreads();
    }
    if (t == 0) g_feat[bc] = red[0] * (1.f / 16384.f);
}

// ---------------- fc1 --------------------------------------------------------
__global__ void __launch_bounds__(256)
fc1_kernel(const float* __restrict__ w, const float* __restrict__ bias) {
    __shared__ float sf[64];
    int b = blockIdx.x, t = threadIdx.x;
    if (t < 64) sf[t] = g_feat[b * 64 + t];
    __syncthreads();
    float s = 0.f;
    const float* wr = w + (size_t)t * 64;
#pragma unroll
    for (int i = 0; i < 64; i++) s = fmaf(wr[i], sf[i], s);
    g_h[b * 256 + t] = s + bias[t];
}

// ---------------- fc2 row + softmax + radius-weighted sum --------------------
__global__ void __launch_bounds__(128)
head_kernel(const float* __restrict__ w, const float* __restrict__ bias) {
    __shared__ float sh[256];
    __shared__ float red[128];
    int j = blockIdx.x;   // 0..99
    int b = blockIdx.y;
    int t = threadIdx.x;
    for (int i = t; i < 256; i += 128) sh[i] = g_h[b * 256 + i];
    __syncthreads();
    float z = -3.4e38f;
    if (t < 100) {
        const float* wr = w + (size_t)(j * 100 + t) * 256;
        float s = 0.f;
        for (int i = 0; i < 256; i++) s = fmaf(wr[i], sh[i], s);
        z = (s + bias[j * 100 + t]) * 0.1f;
    }
    red[t] = z;
    __syncthreads();
    for (int off = 64; off; off >>= 1) {
        if (t < off) red[t] = fmaxf(red[t], red[t + off]);
        __syncthreads();
    }
    float m = red[0];
    __syncthreads();
    float p = (t < 100) ? expf(z - m) : 0.f;
    red[t] = p;
    __syncthreads();
    for (int off = 64; off; off >>= 1) {
        if (t < off) red[t] += red[t + off];
        __syncthreads();
    }
    float S = red[0];
    __syncthreads();
    float rf = ((float)t + 1.0f) * 0.01f;
    red[t] = p * rf;
    __syncthreads();
    for (int off = 64; off; off >>= 1) {
        if (t < off) red[t] += red[t + off];
        __syncthreads();
    }
    if (t == 0) g_vset[b * 100 + j] = red[0] / S;
}

// ---------------- radial mask ------------------------------------------------
__global__ void mask_kernel(float* __restrict__ outMask) {
    int idx = blockIdx.x * blockDim.x + threadIdx.x;
    if (idx >= 8 * NPIX) return;
    int b = idx >> 18;
    int pix = idx & (NPIX - 1);
    int y = pix >> 9, x = pix & 511;
    float dy = (float)y - 256.f, dx = (float)x - 256.f;
    float dist = sqrtf(dy * dy + dx * dx);
    const float MAXR = 362.03867196751236f;
    int lo = 0, hi = 100;
    while (lo < hi) {
        int mid = (lo + hi) >> 1;
        float r = MAXR * (((float)(mid + 1)) * 0.01f);
        if (r <= dist) lo = mid + 1; else hi = mid;
    }
    outMask[idx] = (lo < 100) ? g_vset[b * 100 + lo] : 0.f;
}

// ---------------- inverse FFT rows (fused combine) ---------------------------
__global__ void __launch_bounds__(512)
inv_rows_kernel(const float* __restrict__ maskp) {
    __shared__ float2 sd[8][576];
    __shared__ float2 stw[512];
    int tid = threadIdx.x;
    stw[tid] = g_tw[tid];
    int img = blockIdx.y;     // 0..23
    int r0  = blockIdx.x * 8;
    int b = img / 3;
    size_t base = (size_t)img * NPIX;
#pragma unroll
    for (int row = 0; row < 8; row++) {
        int gr = r0 + row;
        size_t pix = (size_t)gr * 512 + tid;
        float2 n = g_nfq[base + pix];
        float2 c = g_cfq[base + pix];
        float m = maskp[(size_t)b * NPIX +
                        ((size_t)((gr + 256) & 511) << 9) + ((tid + 256) & 511)];
        int p = drev(tid);
        sd[row][FPAD(p)] = make_float2(m * (n.x - c.x), m * (n.y - c.y));
    }
    __syncthreads();
    fft512_stages<1>(sd, stw);
#pragma unroll
    for (int row = 0; row < 8; row++)
        g_nfq[base + (size_t)(r0 + row) * 512 + tid] = sd[row][FPAD(tid)];
}

// ---------------- inverse FFT cols + hard/easy epilogue ----------------------
__global__ void __launch_bounds__(512)
inv_cols_kernel(const float* __restrict__ clean, const float* __restrict__ noisy,
                float* __restrict__ hard, float* __restrict__ easy) {
    __shared__ float2 sd[8][576];
    __shared__ float2 stw[512];
    int tid = threadIdx.x;
    stw[tid] = g_tw[tid];
    int img = blockIdx.y;     // 0..23
    int c0  = blockIdx.x * 8;
    float2* buf = g_nfq + (size_t)img * NPIX;
    int c = tid & 7;
#pragma unroll
    for (int it = 0; it < 8; it++) {
        int r = it * 64 + (tid >> 3);
        float2 v = buf[(size_t)r * 512 + c0 + c];
        int p = drev(r);
        sd[c][FPAD(p)] = v;
    }
    __syncthreads();
    fft512_stages<1>(sd, stw);
    const float scale = 1.f / 262144.f;
#pragma unroll
    for (int it = 0; it < 8; it++) {
        int r = it * 64 + (tid >> 3);
        float re = sd[c][FPAD(r)].x * scale;
        size_t gi = (size_t)img * NPIX + (size_t)r * 512 + c0 + c;
        hard[gi] = clean[gi] + re;
        easy[gi] = noisy[gi] - re;
    }
}

// ---------------- launch ------------------------------------------------------
extern "C" void kernel_launch(void* const* d_in, const int* in_sizes, int n_in,
                              void* d_out, int out_size) {
    const float* clean = (const float*)d_in[0];
    const float* noisy = (const float*)d_in[1];
    const float* c1w = (const float*)d_in[2];
    const float* c1b = (const float*)d_in[3];
    const float* c2w = (const float*)d_in[4];
    const float* c2b = (const float*)d_in[5];
    const float* c3w = (const float*)d_in[6];
    const float* c3b = (const float*)d_in[7];
    const float* f1w = (const float*)d_in[8];
    const float* f1b = (const float*)d_in[9];
    const float* f2w = (const float*)d_in[10];
    const float* f2b = (const float*)d_in[11];

    float* hard  = (float*)d_out;
    float* easy  = hard + 6291456;
    float* maskp = easy + 6291456;

    float *p_fin, *p_p1, *p_p2, *p_y3;
    cudaGetSymbolAddress((void**)&p_fin, g_fin);
    cudaGetSymbolAddress((void**)&p_p1, g_p1);
    cudaGetSymbolAddress((void**)&p_p2, g_p2);
    cudaGetSymbolAddress((void**)&p_y3, g_y3);

    init_tw_kernel<<<1, 512>>>();

    fwd_rows_kernel<<<dim3(64, 48), 512>>>(noisy, clean);
    fwd_cols_kernel<<<dim3(64, 48), 512>>>();

    conv3x3_kernel<12, 4, true,  true ><<<dim3(16, 16, 16), 128>>>(
        nullptr, noisy, clean, p_fin, c1w, c1b, p_p1, 512, 512, 16);
    conv3x3_kernel<16, 4, false, true ><<<dim3(8, 8, 32), 128>>>(
        p_p1, nullptr, nullptr, nullptr, c2w, c2b, p_p2, 256, 256, 32);
    conv3x3_kernel<32, 4, false, false><<<dim3(4, 4, 64), 128>>>(
        p_p2, nullptr, nullptr, nullptr, c3w, c3b, p_y3, 128, 128, 64);

    reduce_mean_kernel<<<512, 256>>>(p_y3);
    fc1_kernel<<<8, 256>>>(f1w, f1b);
    head_kernel<<<dim3(100, 8), 128>>>(f2w, f2b);

    mask_kernel<<<(8 * NPIX + 255) / 256, 256>>>(maskp);
    inv_rows_kernel<<<dim3(64, 24), 512>>>(maskp);
    inv_cols_kernel<<<dim3(64, 24), 512>>>(clean, noisy, hard, easy);
}

// round 3
// speedup vs baseline: 2.0103x; 1.8079x over previous
#include <cuda_runtime.h>
#include <math.h>
#include <stdint.h>

#define NPIX 262144   // 512*512
#define NIMG 24       // 8 batch * 3 channels

// ---------------- scratch (device globals) -----------------------------------
static __device__ float2 g_nfq[NIMG * NPIX];     // noisy spectrum (natural order)
static __device__ float2 g_cfq[NIMG * NPIX];     // clean spectrum
static __device__ float  g_fin[8 * 12 * NPIX];   // filter_input (B,12,512,512)
static __device__ float  g_p1 [8 * 16 * 65536];  // pooled conv1 out (256^2)
static __device__ float  g_p2 [8 * 32 * 16384];  // pooled conv2 out (128^2)
static __device__ float  g_y3 [8 * 64 * 16384];  // conv3 out (128^2)
static __device__ float  g_feat[8 * 64];
static __device__ float  g_h  [8 * 256];
static __device__ float  g_vset[8 * 100];
static __device__ float2 g_tw [512];             // W_512^k

// ---------------- twiddles ---------------------------------------------------
__global__ void init_tw_kernel() {
    int k = threadIdx.x;
    if (k < 512) {
        double s, c;
        sincospi(-(double)k / 256.0, &s, &c);
        g_tw[k] = make_float2((float)c, (float)s);
    }
}

// ---------------- complex helpers --------------------------------------------
__device__ __forceinline__ float2 cadd(float2 a, float2 b){ return make_float2(a.x+b.x, a.y+b.y); }
__device__ __forceinline__ float2 csub(float2 a, float2 b){ return make_float2(a.x-b.x, a.y-b.y); }
template<int INV>
__device__ __forceinline__ float2 ctw(float2 a, float2 w) {
    if (!INV) return make_float2(a.x*w.x - a.y*w.y, a.x*w.y + a.y*w.x);
    else      return make_float2(a.x*w.x + a.y*w.y, a.y*w.x - a.x*w.y);
}

// ---------------- 8-point DFT ------------------------------------------------
template<int INV>
__device__ __forceinline__ void dft8(float2* a) {
    const float C = 0.70710678118654752f;
    float2 b0 = cadd(a[0], a[4]), t4 = csub(a[0], a[4]);
    float2 b1 = cadd(a[1], a[5]), t5 = csub(a[1], a[5]);
    float2 b2 = cadd(a[2], a[6]), t6 = csub(a[2], a[6]);
    float2 b3 = cadd(a[3], a[7]), t7 = csub(a[3], a[7]);
    float2 b5, b6, b7;
    if (!INV) {
        b5 = make_float2(C*(t5.x + t5.y), C*(t5.y - t5.x));
        b6 = make_float2(t6.y, -t6.x);
        b7 = make_float2(C*(t7.y - t7.x), -C*(t7.x + t7.y));
    } else {
        b5 = make_float2(C*(t5.x - t5.y), C*(t5.y + t5.x));
        b6 = make_float2(-t6.y, t6.x);
        b7 = make_float2(-C*(t7.x + t7.y), C*(t7.x - t7.y));
    }
    float2 c0 = cadd(b0, b2), c2 = csub(b0, b2);
    float2 c1 = cadd(b1, b3), t3 = csub(b1, b3);
    float2 c4 = cadd(t4, b6), c6 = csub(t4, b6);
    float2 c5 = cadd(b5, b7), t7b = csub(b5, b7);
    float2 c3 = (!INV) ? make_float2(t3.y, -t3.x)  : make_float2(-t3.y, t3.x);
    float2 c7 = (!INV) ? make_float2(t7b.y, -t7b.x): make_float2(-t7b.y, t7b.x);
    a[0] = cadd(c0, c1); a[4] = csub(c0, c1);
    a[2] = cadd(c2, c3); a[6] = csub(c2, c3);
    a[1] = cadd(c4, c5); a[5] = csub(c4, c5);
    a[3] = cadd(c6, c7); a[7] = csub(c6, c7);
}

#define FPAD(p) ((p) + ((p) >> 3))
__device__ __forceinline__ int drev(int i) {
    return ((i & 7) << 6) | (i & 56) | (i >> 6);
}

template<int INV>
__device__ __forceinline__ void fft512_stages(float2 (*sd)[576], const float2* stw) {
    int tid = threadIdx.x;
    float2* s = sd[tid >> 6];
    int t = tid & 63;
    {
        float2 a[8];
#pragma unroll
        for (int j = 0; j < 8; j++) { int p = 8*t + j; a[j] = s[FPAD(p)]; }
        dft8<INV>(a);
#pragma unroll
        for (int m = 0; m < 8; m++) { int p = 8*t + m; s[FPAD(p)] = a[m]; }
    }
    __syncthreads();
    {
        int k = t & 7, base = ((t >> 3) << 6) + k;
        float2 a[8];
        a[0] = s[FPAD(base)];
#pragma unroll
        for (int j = 1; j < 8; j++) {
            int p = base + 8*j;
            a[j] = ctw<INV>(s[FPAD(p)], stw[8*j*k]);
        }
        dft8<INV>(a);
#pragma unroll
        for (int m = 0; m < 8; m++) { int p = base + 8*m; s[FPAD(p)] = a[m]; }
    }
    __syncthreads();
    {
        float2 a[8];
        a[0] = s[FPAD(t)];
#pragma unroll
        for (int j = 1; j < 8; j++) {
            int p = t + 64*j;
            a[j] = ctw<INV>(s[FPAD(p)], stw[j*t]);
        }
        dft8<INV>(a);
#pragma unroll
        for (int m = 0; m < 8; m++) { int p = t + 64*m; s[FPAD(p)] = a[m]; }
    }
    __syncthreads();
}

// ---------------- forward FFT: rows ------------------------------------------
__global__ void __launch_bounds__(512)
fwd_rows_kernel(const float* __restrict__ noisy, const float* __restrict__ clean) {
    __shared__ float2 sd[8][576];
    __shared__ float2 stw[512];
    int tid = threadIdx.x;
    stw[tid] = g_tw[tid];
    int img = blockIdx.y;
    int r0  = blockIdx.x * 8;
    const float* src = (img < 24) ? (noisy + (size_t)img * NPIX)
                                  : (clean + (size_t)(img - 24) * NPIX);
    float2* dst = ((img < 24) ? g_nfq : g_cfq) + (size_t)(img % 24) * NPIX;
#pragma unroll
    for (int row = 0; row < 8; row++) {
        float v = src[(size_t)(r0 + row) * 512 + tid];
        sd[row][FPAD(drev(tid))] = make_float2(v, 0.f);
    }
    __syncthreads();
    fft512_stages<0>(sd, stw);
#pragma unroll
    for (int row = 0; row < 8; row++)
        dst[(size_t)(r0 + row) * 512 + tid] = sd[row][FPAD(tid)];
}

// ---------------- forward FFT: cols + log-mag epilogue -----------------------
__global__ void __launch_bounds__(512)
fwd_cols_kernel() {
    __shared__ float2 sd[8][576];
    __shared__ float2 stw[512];
    int tid = threadIdx.x;
    stw[tid] = g_tw[tid];
    int img = blockIdx.y;
    int c0  = blockIdx.x * 8;
    int imgl = img % 24;
    float2* buf = ((img < 24) ? g_nfq : g_cfq) + (size_t)imgl * NPIX;
    int c = tid & 7;
#pragma unroll
    for (int it = 0; it < 8; it++) {
        int r = it * 64 + (tid >> 3);
        sd[c][FPAD(drev(r))] = buf[(size_t)r * 512 + c0 + c];
    }
    __syncthreads();
    fft512_stages<0>(sd, stw);
    int b = imgl / 3, ch = imgl % 3;
    int chbase = (img < 24) ? 3 : 9;
    float* fin = g_fin + (size_t)(b * 12 + chbase + ch) * NPIX;
#pragma unroll
    for (int it = 0; it < 8; it++) {
        int r = it * 64 + (tid >> 3);
        float2 v = sd[c][FPAD(r)];
        buf[(size_t)r * 512 + c0 + c] = v;
        int ys = (r + 256) & 511, xs = (c0 + c + 256) & 511;
        fin[(size_t)ys * 512 + xs] = log10f(sqrtf(v.x * v.x + v.y * v.y) + 1.f);
    }
}

// ---------------- spatial channels into filter_input -------------------------
__global__ void copy_spatial_kernel(const float* __restrict__ noisy,
                                    const float* __restrict__ clean) {
    int idx = blockIdx.x * blockDim.x + threadIdx.x;
    if (idx >= 8 * 3 * NPIX) return;
    int b = idx / (3 * NPIX);
    int c = (idx / NPIX) % 3;
    int pix = idx & (NPIX - 1);
    g_fin[(size_t)(b * 12 + c) * NPIX + pix]     = noisy[idx];
    g_fin[(size_t)(b * 12 + 6 + c) * NPIX + pix] = clean[idx];
}

// ---------------- tf32 conversion --------------------------------------------
__device__ __forceinline__ unsigned f2tf(float f) {
    unsigned r;
    asm("cvt.rna.tf32.f32 %0, %1;" : "=r"(r) : "f"(f));
    return r;
}

#define MMA_TF32(d, a0,a1,a2,a3, b0,b1)                                        \
    asm("mma.sync.aligned.m16n8k8.row.col.f32.tf32.tf32.f32 "                  \
        "{%0,%1,%2,%3}, {%4,%5,%6,%7}, {%8,%9}, {%0,%1,%2,%3};"                \
        : "+f"(d[0]), "+f"(d[1]), "+f"(d[2]), "+f"(d[3])                       \
        : "r"(a0), "r"(a1), "r"(a2), "r"(a3), "r"(b0), "r"(b1))

// ---------------- implicit-GEMM 3x3 conv on tensor cores ---------------------
// block 256 thr, pixel tile 32x x 16y, 16 couts per block.
// M=16 x-pixels, N=8 couts, K = 9*CIN (padded to KP, mult of 8).
// smem: sIn[CIN][18][36] tf32, wT[KP][24] tf32 (cout-major rows), lut[KP].
template<int CIN, int COUT, int H, int W, bool POOL>
__global__ void __launch_bounds__(256)
convmma_kernel(const float* __restrict__ in, const float* __restrict__ wgt,
               const float* __restrict__ bias, float* __restrict__ out) {
    constexpr int K  = CIN * 9;
    constexpr int KP = (K + 7) & ~7;
    constexpr int SINN = CIN * 648;        // 18*36
    constexpr int OGC = COUT / 16;

    extern __shared__ float smem[];
    float* sIn = smem;
    float* wT  = smem + SINN;
    int*   lut = (int*)(smem + SINN + KP * 24);

    int tid = threadIdx.x;
    int bz = blockIdx.z;
    int og = bz % OGC;
    int b  = bz / OGC;
    int x0 = blockIdx.x * 32, y0 = blockIdx.y * 16;

    // ---- fill lut
    for (int k = tid; k < KP; k += 256) {
        int v = 0;
        if (k < K) { int ic = k / 9, r = k % 9; v = ic * 648 + (r / 3) * 36 + (r % 3); }
        lut[k] = v;
    }
    // ---- fill weights (transposed, tf32)
    for (int e = tid; e < KP * 16; e += 256) {
        int k = e >> 4, o = e & 15;
        float wv = (k < K) ? wgt[(og * 16 + o) * K + k] : 0.f;
        wT[k * 24 + o] = __uint_as_float(f2tf(wv));
    }
    // ---- fill input tile (halo, tf32)
    for (int e = tid; e < SINN; e += 256) {
        int ic = e / 648;
        int rr = e - ic * 648;
        int r = rr / 36, cc = rr - r * 36;
        int gy = y0 + r - 1, gx = x0 + cc - 1;
        float v = 0.f;
        if (cc < 34 && (unsigned)gy < (unsigned)H && (unsigned)gx < (unsigned)W)
            v = in[((size_t)(b * CIN + ic) * H + gy) * W + gx];
        sIn[e] = __uint_as_float(f2tf(v));
    }
    __syncthreads();

    int lane = tid & 31, w = tid >> 5;
    int gid = lane >> 2, tig = lane & 3;

    float acc[4][2][4];
#pragma unroll
    for (int mt = 0; mt < 4; mt++)
#pragma unroll
        for (int nt = 0; nt < 2; nt++)
#pragma unroll
            for (int c = 0; c < 4; c++) acc[mt][nt][c] = 0.f;

    int moff[4];
#pragma unroll
    for (int mt = 0; mt < 4; mt++)
        moff[mt] = (2 * w + (mt & 1)) * 36 + (mt >> 1) * 16 + gid;

#pragma unroll 2
    for (int kc = 0; kc < KP / 8; kc++) {
        int kb = kc * 8;
        int l0 = lut[kb + tig];
        int l1 = lut[kb + tig + 4];
        unsigned bf0[2], bf1[2];
#pragma unroll
        for (int nt = 0; nt < 2; nt++) {
            bf0[nt] = __float_as_uint(wT[(kb + tig) * 24 + nt * 8 + gid]);
            bf1[nt] = __float_as_uint(wT[(kb + tig + 4) * 24 + nt * 8 + gid]);
        }
#pragma unroll
        for (int mt = 0; mt < 4; mt++) {
            unsigned a0 = __float_as_uint(sIn[l0 + moff[mt]]);
            unsigned a1 = __float_as_uint(sIn[l0 + moff[mt] + 8]);
            unsigned a2 = __float_as_uint(sIn[l1 + moff[mt]]);
            unsigned a3 = __float_as_uint(sIn[l1 + moff[mt] + 8]);
#pragma unroll
            for (int nt = 0; nt < 2; nt++)
                MMA_TF32(acc[mt][nt], a0, a1, a2, a3, bf0[nt], bf1[nt]);
        }
    }

    // ---- epilogue
    if (POOL) {
        const int Ho = H / 2, Wo = W / 2;
        int oy = (y0 >> 1) + w;
#pragma unroll
        for (int half = 0; half < 2; half++) {
#pragma unroll
            for (int nt = 0; nt < 2; nt++)
#pragma unroll
                for (int c = 0; c < 2; c++) {
                    int o = og * 16 + nt * 8 + 2 * tig + c;
                    float bv = bias[o];
                    float sa = fmaxf(acc[half*2][nt][c]   + bv, 0.f) +
                               fmaxf(acc[half*2+1][nt][c] + bv, 0.f);
                    float sb = fmaxf(acc[half*2][nt][c+2]   + bv, 0.f) +
                               fmaxf(acc[half*2+1][nt][c+2] + bv, 0.f);
                    sa += __shfl_xor_sync(0xffffffffu, sa, 4);
                    sb += __shfl_xor_sync(0xffffffffu, sb, 4);
                    if (!(gid & 1)) {
                        int oxa = (x0 + half * 16 + gid) >> 1;
                        size_t base = ((size_t)(b * COUT + o) * Ho + oy) * Wo;
                        out[base + oxa]     = 0.25f * sa;
                        out[base + oxa + 4] = 0.25f * sb;
                    }
                }
        }
    } else {
#pragma unroll
        for (int mt = 0; mt < 4; mt++) {
            int Y = y0 + 2 * w + (mt & 1);
            int X = x0 + (mt >> 1) * 16 + gid;
#pragma unroll
            for (int nt = 0; nt < 2; nt++)
#pragma unroll
                for (int c = 0; c < 2; c++) {
                    int o = og * 16 + nt * 8 + 2 * tig + c;
                    float bv = bias[o];
                    size_t base = ((size_t)(b * COUT + o) * H + Y) * W + X;
                    out[base]     = fmaxf(acc[mt][nt][c]   + bv, 0.f);
                    out[base + 8] = fmaxf(acc[mt][nt][c+2] + bv, 0.f);
                }
        }
    }
}

// ---------------- global mean over 128x128 -----------------------------------
__global__ void __launch_bounds__(256)
reduce_mean_kernel(const float* __restrict__ y3) {
    __shared__ float red[256];
    int bc = blockIdx.x;
    int t  = threadIdx.x;
    const float* p = y3 + (size_t)bc * 16384;
    float s = 0.f;
    for (int i = t; i < 16384; i += 256) s += p[i];
    red[t] = s;
    __syncthreads();
    for (int off = 128; off; off >>= 1) {
        if (t < off) red[t] += red[t + off];
        __syncthreads();
    }
    if (t == 0) g_feat[bc] = red[0] * (1.f / 16384.f);
}

// ---------------- fc1 --------------------------------------------------------
__global__ void __launch_bounds__(256)
fc1_kernel(const float* __restrict__ w, const float* __restrict__ bias) {
    __shared__ float sf[64];
    int b = blockIdx.x, t = threadIdx.x;
    if (t < 64) sf[t] = g_feat[b * 64 + t];
    __syncthreads();
    float s = 0.f;
    const float* wr = w + (size_t)t * 64;
#pragma unroll
    for (int i = 0; i < 64; i++) s = fmaf(wr[i], sf[i], s);
    g_h[b * 256 + t] = s + bias[t];
}

// ---------------- head -------------------------------------------------------
__global__ void __launch_bounds__(128)
head_kernel(const float* __restrict__ w, const float* __restrict__ bias) {
    __shared__ float sh[256];
    __shared__ float red[128];
    int j = blockIdx.x;
    int b = blockIdx.y;
    int t = threadIdx.x;
    for (int i = t; i < 256; i += 128) sh[i] = g_h[b * 256 + i];
    __syncthreads();
    float z = -3.4e38f;
    if (t < 100) {
        const float* wr = w + (size_t)(j * 100 + t) * 256;
        float s = 0.f;
        for (int i = 0; i < 256; i++) s = fmaf(wr[i], sh[i], s);
        z = (s + bias[j * 100 + t]) * 0.1f;
    }
    red[t] = z;
    __syncthreads();
    for (int off = 64; off; off >>= 1) {
        if (t < off) red[t] = fmaxf(red[t], red[t + off]);
        __syncthreads();
    }
    float m = red[0];
    __syncthreads();
    float p = (t < 100) ? expf(z - m) : 0.f;
    red[t] = p;
    __syncthreads();
    for (int off = 64; off; off >>= 1) {
        if (t < off) red[t] += red[t + off];
        __syncthreads();
    }
    float S = red[0];
    __syncthreads();
    float rf = ((float)t + 1.0f) * 0.01f;
    red[t] = p * rf;
    __syncthreads();
    for (int off = 64; off; off >>= 1) {
        if (t < off) red[t] += red[t + off];
        __syncthreads();
    }
    if (t == 0) g_vset[b * 100 + j] = red[0] / S;
}

// ---------------- radial mask ------------------------------------------------
__global__ void mask_kernel(float* __restrict__ outMask) {
    int idx = blockIdx.x * blockDim.x + threadIdx.x;
    if (idx >= 8 * NPIX) return;
    int b = idx >> 18;
    int pix = idx & (NPIX - 1);
    int y = pix >> 9, x = pix & 511;
    float dy = (float)y - 256.f, dx = (float)x - 256.f;
    float dist = sqrtf(dy * dy + dx * dx);
    const float MAXR = 362.03867196751236f;
    int lo = 0, hi = 100;
    while (lo < hi) {
        int mid = (lo + hi) >> 1;
        float r = MAXR * (((float)(mid + 1)) * 0.01f);
        if (r <= dist) lo = mid + 1; else hi = mid;
    }
    outMask[idx] = (lo < 100) ? g_vset[b * 100 + lo] : 0.f;
}

// ---------------- inverse FFT rows (fused combine) ---------------------------
__global__ void __launch_bounds__(512)
inv_rows_kernel(const float* __restrict__ maskp) {
    __shared__ float2 sd[8][576];
    __shared__ float2 stw[512];
    int tid = threadIdx.x;
    stw[tid] = g_tw[tid];
    int img = blockIdx.y;
    int r0  = blockIdx.x * 8;
    int b = img / 3;
    size_t base = (size_t)img * NPIX;
#pragma unroll
    for (int row = 0; row < 8; row++) {
        int gr = r0 + row;
        size_t pix = (size_t)gr * 512 + tid;
        float2 n = g_nfq[base + pix];
        float2 c = g_cfq[base + pix];
        float m = maskp[(size_t)b * NPIX +
                        ((size_t)((gr + 256) & 511) << 9) + ((tid + 256) & 511)];
        sd[row][FPAD(drev(tid))] = make_float2(m * (n.x - c.x), m * (n.y - c.y));
    }
    __syncthreads();
    fft512_stages<1>(sd, stw);
#pragma unroll
    for (int row = 0; row < 8; row++)
        g_nfq[base + (size_t)(r0 + row) * 512 + tid] = sd[row][FPAD(tid)];
}

// ---------------- inverse FFT cols + hard/easy -------------------------------
__global__ void __launch_bounds__(512)
inv_cols_kernel(const float* __restrict__ clean, const float* __restrict__ noisy,
                float* __restrict__ hard, float* __restrict__ easy) {
    __shared__ float2 sd[8][576];
    __shared__ float2 stw[512];
    int tid = threadIdx.x;
    stw[tid] = g_tw[tid];
    int img = blockIdx.y;
    int c0  = blockIdx.x * 8;
    float2* buf = g_nfq + (size_t)img * NPIX;
    int c = tid & 7;
#pragma unroll
    for (int it = 0; it < 8; it++) {
        int r = it * 64 + (tid >> 3);
        sd[c][FPAD(drev(r))] = buf[(size_t)r * 512 + c0 + c];
    }
    __syncthreads();
    fft512_stages<1>(sd, stw);
    const float scale = 1.f / 262144.f;
#pragma unroll
    for (int it = 0; it < 8; it++) {
        int r = it * 64 + (tid >> 3);
        float re = sd[c][FPAD(r)].x * scale;
        size_t gi = (size_t)img * NPIX + (size_t)r * 512 + c0 + c;
        hard[gi] = clean[gi] + re;
        easy[gi] = noisy[gi] - re;
    }
}

// ---------------- launch ------------------------------------------------------
extern "C" void kernel_launch(void* const* d_in, const int* in_sizes, int n_in,
                              void* d_out, int out_size) {
    const float* clean = (const float*)d_in[0];
    const float* noisy = (const float*)d_in[1];
    const float* c1w = (const float*)d_in[2];
    const float* c1b = (const float*)d_in[3];
    const float* c2w = (const float*)d_in[4];
    const float* c2b = (const float*)d_in[5];
    const float* c3w = (const float*)d_in[6];
    const float* c3b = (const float*)d_in[7];
    const float* f1w = (const float*)d_in[8];
    const float* f1b = (const float*)d_in[9];
    const float* f2w = (const float*)d_in[10];
    const float* f2b = (const float*)d_in[11];

    float* hard  = (float*)d_out;
    float* easy  = hard + 6291456;
    float* maskp = easy + 6291456;

    float *p_fin, *p_p1, *p_p2, *p_y3;
    cudaGetSymbolAddress((void**)&p_fin, g_fin);
    cudaGetSymbolAddress((void**)&p_p1, g_p1);
    cudaGetSymbolAddress((void**)&p_p2, g_p2);
    cudaGetSymbolAddress((void**)&p_y3, g_y3);

    // dynamic smem sizes: sIn + wT + lut (floats/ints *4)
    const int smem1 = (12 * 648 + 112 * 24 + 112) * 4;   // 42304
    const int smem2 = (16 * 648 + 144 * 24 + 144) * 4;   // 55872
    const int smem3 = (32 * 648 + 288 * 24 + 288) * 4;   // 111744
    cudaFuncSetAttribute(convmma_kernel<12, 16, 512, 512, true>,
                         cudaFuncAttributeMaxDynamicSharedMemorySize, smem1);
    cudaFuncSetAttribute(convmma_kernel<16, 32, 256, 256, true>,
                         cudaFuncAttributeMaxDynamicSharedMemorySize, smem2);
    cudaFuncSetAttribute(convmma_kernel<32, 64, 128, 128, false>,
                         cudaFuncAttributeMaxDynamicSharedMemorySize, smem3);

    init_tw_kernel<<<1, 512>>>();

    fwd_rows_kernel<<<dim3(64, 48), 512>>>(noisy, clean);
    fwd_cols_kernel<<<dim3(64, 48), 512>>>();
    copy_spatial_kernel<<<(8 * 3 * NPIX + 255) / 256, 256>>>(noisy, clean);

    convmma_kernel<12, 16, 512, 512, true><<<dim3(16, 32, 8), 256, smem1>>>(
        p_fin, c1w, c1b, p_p1);
    convmma_kernel<16, 32, 256, 256, true><<<dim3(8, 16, 16), 256, smem2>>>(
        p_p1, c2w, c2b, p_p2);
    convmma_kernel<32, 64, 128, 128, false><<<dim3(4, 8, 32), 256, smem3>>>(
        p_p2, c3w, c3b, p_y3);

    reduce_mean_kernel<<<512, 256>>>(p_y3);
    fc1_kernel<<<8, 256>>>(f1w, f1b);
    head_kernel<<<dim3(100, 8), 128>>>(f2w, f2b);

    mask_kernel<<<(8 * NPIX + 255) / 256, 256>>>(maskp);
    inv_rows_kernel<<<dim3(64, 24), 512>>>(maskp);
    inv_cols_kernel<<<dim3(64, 24), 512>>>(clean, noisy, hard, easy);
}

// round 5
// speedup vs baseline: 2.1042x; 1.0467x over previous
#include <cuda_runtime.h>
#include <math.h>
#include <stdint.h>

#define NPIX 262144   // 512*512
#define NIMG 24       // 8 batch * 3 channels

// ---------------- scratch (device globals) -----------------------------------
static __device__ float2 g_nfq[NIMG * NPIX];     // packed spectrum Z = FFT(noisy + i*clean)
static __device__ float2 g_cfq[NIMG * NPIX];     // inverse-pass intermediate (12 pair images)
static __device__ float  g_fin[8 * 6 * NPIX];    // log-mag channels (B,6,512,512)
static __device__ float  g_p1 [8 * 16 * 65536];  // pooled conv1 out (256^2)
static __device__ float  g_p2 [8 * 32 * 16384];  // pooled conv2 out (128^2)
static __device__ float  g_y3 [8 * 64 * 16384];  // conv3 out (128^2)
static __device__ float  g_feat[8 * 64];
static __device__ float  g_h  [8 * 256];
static __device__ float  g_vset[8 * 100];
static __device__ float2 g_tw [512];             // W_512^k

// ---------------- twiddles ---------------------------------------------------
__global__ void init_tw_kernel() {
    int k = threadIdx.x;
    if (k < 512) {
        double s, c;
        sincospi(-(double)k / 256.0, &s, &c);
        g_tw[k] = make_float2((float)c, (float)s);
    }
}

// ---------------- complex helpers --------------------------------------------
__device__ __forceinline__ float2 cadd(float2 a, float2 b){ return make_float2(a.x+b.x, a.y+b.y); }
__device__ __forceinline__ float2 csub(float2 a, float2 b){ return make_float2(a.x-b.x, a.y-b.y); }
template<int INV>
__device__ __forceinline__ float2 ctw(float2 a, float2 w) {
    if (!INV) return make_float2(a.x*w.x - a.y*w.y, a.x*w.y + a.y*w.x);
    else      return make_float2(a.x*w.x + a.y*w.y, a.y*w.x - a.x*w.y);
}

// ---------------- 8-point DFT ------------------------------------------------
template<int INV>
__device__ __forceinline__ void dft8(float2* a) {
    const float C = 0.70710678118654752f;
    float2 b0 = cadd(a[0], a[4]), t4 = csub(a[0], a[4]);
    float2 b1 = cadd(a[1], a[5]), t5 = csub(a[1], a[5]);
    float2 b2 = cadd(a[2], a[6]), t6 = csub(a[2], a[6]);
    float2 b3 = cadd(a[3], a[7]), t7 = csub(a[3], a[7]);
    float2 b5, b6, b7;
    if (!INV) {
        b5 = make_float2(C*(t5.x + t5.y), C*(t5.y - t5.x));
        b6 = make_float2(t6.y, -t6.x);
        b7 = make_float2(C*(t7.y - t7.x), -C*(t7.x + t7.y));
    } else {
        b5 = make_float2(C*(t5.x - t5.y), C*(t5.y + t5.x));
        b6 = make_float2(-t6.y, t6.x);
        b7 = make_float2(-C*(t7.x + t7.y), C*(t7.x - t7.y));
    }
    float2 c0 = cadd(b0, b2), c2 = csub(b0, b2);
    float2 c1 = cadd(b1, b3), t3 = csub(b1, b3);
    float2 c4 = cadd(t4, b6), c6 = csub(t4, b6);
    float2 c5 = cadd(b5, b7), t7b = csub(b5, b7);
    float2 c3 = (!INV) ? make_float2(t3.y, -t3.x)  : make_float2(-t3.y, t3.x);
    float2 c7 = (!INV) ? make_float2(t7b.y, -t7b.x): make_float2(-t7b.y, t7b.x);
    a[0] = cadd(c0, c1); a[4] = csub(c0, c1);
    a[2] = cadd(c2, c3); a[6] = csub(c2, c3);
    a[1] = cadd(c4, c5); a[5] = csub(c4, c5);
    a[3] = cadd(c6, c7); a[7] = csub(c6, c7);
}

#define FPAD(p) ((p) + ((p) >> 3))
__device__ __forceinline__ int drev(int i) {
    return ((i & 7) << 6) | (i & 56) | (i >> 6);
}

template<int INV>
__device__ __forceinline__ void fft512_stages(float2 (*sd)[576], const float2* stw) {
    int tid = threadIdx.x;
    float2* s = sd[tid >> 6];
    int t = tid & 63;
    {
        float2 a[8];
#pragma unroll
        for (int j = 0; j < 8; j++) { int p = 8*t + j; a[j] = s[FPAD(p)]; }
        dft8<INV>(a);
#pragma unroll
        for (int m = 0; m < 8; m++) { int p = 8*t + m; s[FPAD(p)] = a[m]; }
    }
    __syncthreads();
    {
        int k = t & 7, base = ((t >> 3) << 6) + k;
        float2 a[8];
        a[0] = s[FPAD(base)];
#pragma unroll
        for (int j = 1; j < 8; j++) {
            int p = base + 8*j;
            a[j] = ctw<INV>(s[FPAD(p)], stw[8*j*k]);
        }
        dft8<INV>(a);
#pragma unroll
        for (int m = 0; m < 8; m++) { int p = base + 8*m; s[FPAD(p)] = a[m]; }
    }
    __syncthreads();
    {
        float2 a[8];
        a[0] = s[FPAD(t)];
#pragma unroll
        for (int j = 1; j < 8; j++) {
            int p = t + 64*j;
            a[j] = ctw<INV>(s[FPAD(p)], stw[j*t]);
        }
        dft8<INV>(a);
#pragma unroll
        for (int m = 0; m < 8; m++) { int p = t + 64*m; s[FPAD(p)] = a[m]; }
    }
    __syncthreads();
}

// ---------------- forward FFT rows: z = noisy + i*clean ----------------------
__global__ void __launch_bounds__(512)
fwd_rows_kernel(const float* __restrict__ noisy, const float* __restrict__ clean) {
    __shared__ float2 sd[8][576];
    __shared__ float2 stw[512];
    int tid = threadIdx.x;
    stw[tid] = g_tw[tid];
    int img = blockIdx.y;            // 0..23
    int r0  = blockIdx.x * 8;
    size_t base = (size_t)img * NPIX;
#pragma unroll
    for (int row = 0; row < 8; row++) {
        size_t gi = base + (size_t)(r0 + row) * 512 + tid;
        sd[row][FPAD(drev(tid))] = make_float2(noisy[gi], clean[gi]);
    }
    __syncthreads();
    fft512_stages<0>(sd, stw);
#pragma unroll
    for (int row = 0; row < 8; row++)
        g_nfq[base + (size_t)(r0 + row) * 512 + tid] = sd[row][FPAD(tid)];
}

// ---------------- forward FFT cols -------------------------------------------
__global__ void __launch_bounds__(512)
fwd_cols_kernel() {
    __shared__ float2 sd[8][576];
    __shared__ float2 stw[512];
    int tid = threadIdx.x;
    stw[tid] = g_tw[tid];
    int img = blockIdx.y;            // 0..23
    int c0  = blockIdx.x * 8;
    float2* buf = g_nfq + (size_t)img * NPIX;
    int c = tid & 7;
#pragma unroll
    for (int it = 0; it < 8; it++) {
        int r = it * 64 + (tid >> 3);
        sd[c][FPAD(drev(r))] = buf[(size_t)r * 512 + c0 + c];
    }
    __syncthreads();
    fft512_stages<0>(sd, stw);
#pragma unroll
    for (int it = 0; it < 8; it++) {
        int r = it * 64 + (tid >> 3);
        buf[(size_t)r * 512 + c0 + c] = sd[c][FPAD(r)];
    }
}

// ---------------- unpack Hermitian pair -> log-mag channels ------------------
__global__ void unpack_logmag_kernel() {
    int idx = blockIdx.x * blockDim.x + threadIdx.x;
    if (idx >= NIMG * NPIX) return;
    int img = idx >> 18;
    int pix = idx & (NPIX - 1);
    int r = pix >> 9, c = pix & 511;
    int mr = (512 - r) & 511, mc = (512 - c) & 511;
    float2 Zk = g_nfq[(size_t)img * NPIX + pix];
    float2 Zm = g_nfq[(size_t)img * NPIX + (mr << 9) + mc];
    float Nx = 0.5f * (Zk.x + Zm.x), Ny = 0.5f * (Zk.y - Zm.y);
    float Dx = 0.5f * (Zk.x - Zm.x), Dy = 0.5f * (Zk.y + Zm.y);
    // C = Dy - i*Dx  -> |C| = sqrt(Dx^2+Dy^2)
    int b = img / 3, ch = img - 3 * b;
    int ys = (r + 256) & 511, xs = (c + 256) & 511;
    size_t off = ((size_t)ys << 9) + xs;
    g_fin[(size_t)(b * 6 + ch) * NPIX + off]     = log10f(sqrtf(Nx*Nx + Ny*Ny) + 1.f);
    g_fin[(size_t)(b * 6 + 3 + ch) * NPIX + off] = log10f(sqrtf(Dx*Dx + Dy*Dy) + 1.f);
}

// ---------------- tf32 conversion --------------------------------------------
__device__ __forceinline__ unsigned f2tf(float f) {
    unsigned r;
    asm("cvt.rna.tf32.f32 %0, %1;" : "=r"(r) : "f"(f));
    return r;
}

#define MMA_TF32(d, a0,a1,a2,a3, b0,b1)                                        \
    asm("mma.sync.aligned.m16n8k8.row.col.f32.tf32.tf32.f32 "                  \
        "{%0,%1,%2,%3}, {%4,%5,%6,%7}, {%8,%9}, {%0,%1,%2,%3};"                \
        : "+f"(d[0]), "+f"(d[1]), "+f"(d[2]), "+f"(d[3])                       \
        : "r"(a0), "r"(a1), "r"(a2), "r"(a3), "r"(b0), "r"(b1))

// ---------------- implicit-GEMM 3x3 conv on tensor cores ---------------------
template<int CIN, int COUT, int H, int W, bool POOL, bool GATHER>
__global__ void __launch_bounds__(256)
convmma_kernel(const float* __restrict__ in,
               const float* __restrict__ noisy, const float* __restrict__ clean,
               const float* __restrict__ fin,
               const float* __restrict__ wgt,
               const float* __restrict__ bias, float* __restrict__ out) {
    constexpr int K  = CIN * 9;
    constexpr int KP = (K + 7) & ~7;
    constexpr int SINN = CIN * 648;        // 18*36
    constexpr int OGC = COUT / 16;

    extern __shared__ float smem[];
    float* sIn = smem;
    float* wT  = smem + SINN;
    int*   lut = (int*)(smem + SINN + KP * 24);

    int tid = threadIdx.x;
    int bz = blockIdx.z;
    int og = bz % OGC;
    int b  = bz / OGC;
    int x0 = blockIdx.x * 32, y0 = blockIdx.y * 16;

    for (int k = tid; k < KP; k += 256) {
        int v = 0;
        if (k < K) { int ic = k / 9, r = k % 9; v = ic * 648 + (r / 3) * 36 + (r % 3); }
        lut[k] = v;
    }
    for (int e = tid; e < KP * 16; e += 256) {
        int k = e >> 4, o = e & 15;
        float wv = (k < K) ? wgt[(og * 16 + o) * K + k] : 0.f;
        wT[k * 24 + o] = __uint_as_float(f2tf(wv));
    }
    for (int e = tid; e < SINN; e += 256) {
        int ic = e / 648;
        int rr = e - ic * 648;
        int r = rr / 36, cc = rr - r * 36;
        int gy = y0 + r - 1, gx = x0 + cc - 1;
        float v = 0.f;
        if (cc < 34 && (unsigned)gy < (unsigned)H && (unsigned)gx < (unsigned)W) {
            if (GATHER) {
                int grp = ic / 3, sub = ic - 3 * grp;
                const float* src =
                    (grp == 0) ? noisy + (size_t)(b * 3 + sub) * NPIX :
                    (grp == 1) ? fin   + (size_t)(b * 6 + sub) * NPIX :
                    (grp == 2) ? clean + (size_t)(b * 3 + sub) * NPIX :
                                 fin   + (size_t)(b * 6 + 3 + sub) * NPIX;
                v = src[((size_t)gy << 9) + gx];
            } else {
                v = in[((size_t)(b * CIN + ic) * H + gy) * W + gx];
            }
        }
        sIn[e] = __uint_as_float(f2tf(v));
    }
    __syncthreads();

    int lane = tid & 31, w = tid >> 5;
    int gid = lane >> 2, tig = lane & 3;

    float acc[4][2][4];
#pragma unroll
    for (int mt = 0; mt < 4; mt++)
#pragma unroll
        for (int nt = 0; nt < 2; nt++)
#pragma unroll
            for (int c = 0; c < 4; c++) acc[mt][nt][c] = 0.f;

    int moff[4];
#pragma unroll
    for (int mt = 0; mt < 4; mt++)
        moff[mt] = (2 * w + (mt & 1)) * 36 + (mt >> 1) * 16 + gid;

#pragma unroll 2
    for (int kc = 0; kc < KP / 8; kc++) {
        int kb = kc * 8;
        int l0 = lut[kb + tig];
        int l1 = lut[kb + tig + 4];
        unsigned bf0[2], bf1[2];
#pragma unroll
        for (int nt = 0; nt < 2; nt++) {
            bf0[nt] = __float_as_uint(wT[(kb + tig) * 24 + nt * 8 + gid]);
            bf1[nt] = __float_as_uint(wT[(kb + tig + 4) * 24 + nt * 8 + gid]);
        }
#pragma unroll
        for (int mt = 0; mt < 4; mt++) {
            unsigned a0 = __float_as_uint(sIn[l0 + moff[mt]]);
            unsigned a1 = __float_as_uint(sIn[l0 + moff[mt] + 8]);
            unsigned a2 = __float_as_uint(sIn[l1 + moff[mt]]);
            unsigned a3 = __float_as_uint(sIn[l1 + moff[mt] + 8]);
#pragma unroll
            for (int nt = 0; nt < 2; nt++)
                MMA_TF32(acc[mt][nt], a0, a1, a2, a3, bf0[nt], bf1[nt]);
        }
    }

    if (POOL) {
        const int Ho = H / 2, Wo = W / 2;
        int oy = (y0 >> 1) + w;
#pragma unroll
        for (int half = 0; half < 2; half++) {
#pragma unroll
            for (int nt = 0; nt < 2; nt++)
#pragma unroll
                for (int c = 0; c < 2; c++) {
                    int o = og * 16 + nt * 8 + 2 * tig + c;
                    float bv = bias[o];
                    float sa = fmaxf(acc[half*2][nt][c]   + bv, 0.f) +
                               fmaxf(acc[half*2+1][nt][c] + bv, 0.f);
                    float sb = fmaxf(acc[half*2][nt][c+2]   + bv, 0.f) +
                               fmaxf(acc[half*2+1][nt][c+2] + bv, 0.f);
                    sa += __shfl_xor_sync(0xffffffffu, sa, 4);
                    sb += __shfl_xor_sync(0xffffffffu, sb, 4);
                    if (!(gid & 1)) {
                        int oxa = (x0 + half * 16 + gid) >> 1;
                        size_t base = ((size_t)(b * COUT + o) * Ho + oy) * Wo;
                        out[base + oxa]     = 0.25f * sa;
                        out[base + oxa + 4] = 0.25f * sb;
                    }
                }
        }
    } else {
#pragma unroll
        for (int mt = 0; mt < 4; mt++) {
            int Y = y0 + 2 * w + (mt & 1);
            int X = x0 + (mt >> 1) * 16 + gid;
#pragma unroll
            for (int nt = 0; nt < 2; nt++)
#pragma unroll
                for (int c = 0; c < 2; c++) {
                    int o = og * 16 + nt * 8 + 2 * tig + c;
                    float bv = bias[o];
                    size_t base = ((size_t)(b * COUT + o) * H + Y) * W + X;
                    out[base]     = fmaxf(acc[mt][nt][c]   + bv, 0.f);
                    out[base + 8] = fmaxf(acc[mt][nt][c+2] + bv, 0.f);
                }
        }
    }
}

// ---------------- global mean over 128x128 -----------------------------------
__global__ void __launch_bounds__(256)
reduce_mean_kernel(const float* __restrict__ y3) {
    __shared__ float red[256];
    int bc = blockIdx.x;
    int t  = threadIdx.x;
    const float* p = y3 + (size_t)bc * 16384;
    float s = 0.f;
    for (int i = t; i < 16384; i += 256) s += p[i];
    red[t] = s;
    __syncthreads();
    for (int off = 128; off; off >>= 1) {
        if (t < off) red[t] += red[t + off];
        __syncthreads();
    }
    if (t == 0) g_feat[bc] = red[0] * (1.f / 16384.f);
}

// ---------------- fc1 --------------------------------------------------------
__global__ void __launch_bounds__(256)
fc1_kernel(const float* __restrict__ w, const float* __restrict__ bias) {
    __shared__ float sf[64];
    int b = blockIdx.x, t = threadIdx.x;
    if (t < 64) sf[t] = g_feat[b * 64 + t];
    __syncthreads();
    float s = 0.f;
    const float* wr = w + (size_t)t * 64;
#pragma unroll
    for (int i = 0; i < 64; i++) s = fmaf(wr[i], sf[i], s);
    g_h[b * 256 + t] = s + bias[t];
}

// ---------------- head -------------------------------------------------------
__global__ void __launch_bounds__(128)
head_kernel(const float* __restrict__ w, const float* __restrict__ bias) {
    __shared__ float sh[256];
    __shared__ float red[128];
    int j = blockIdx.x;
    int b = blockIdx.y;
    int t = threadIdx.x;
    for (int i = t; i < 256; i += 128) sh[i] = g_h[b * 256 + i];
    __syncthreads();
    float z = -3.4e38f;
    if (t < 100) {
        const float* wr = w + (size_t)(j * 100 + t) * 256;
        float s = 0.f;
        for (int i = 0; i < 256; i++) s = fmaf(wr[i], sh[i], s);
        z = (s + bias[j * 100 + t]) * 0.1f;
    }
    red[t] = z;
    __syncthreads();
    for (int off = 64; off; off >>= 1) {
        if (t < off) red[t] = fmaxf(red[t], red[t + off]);
        __syncthreads();
    }
    float m = red[0];
    __syncthreads();
    float p = (t < 100) ? expf(z - m) : 0.f;
    red[t] = p;
    __syncthreads();
    for (int off = 64; off; off >>= 1) {
        if (t < off) red[t] += red[t + off];
        __syncthreads();
    }
    float S = red[0];
    __syncthreads();
    float rf = ((float)t + 1.0f) * 0.01f;
    red[t] = p * rf;
    __syncthreads();
    for (int off = 64; off; off >>= 1) {
        if (t < off) red[t] += red[t + off];
        __syncthreads();
    }
    if (t == 0) g_vset[b * 100 + j] = red[0] / S;
}

// ---------------- radial mask ------------------------------------------------
__global__ void mask_kernel(float* __restrict__ outMask) {
    int idx = blockIdx.x * blockDim.x + threadIdx.x;
    if (idx >= 8 * NPIX) return;
    int b = idx >> 18;
    int pix = idx & (NPIX - 1);
    int y = pix >> 9, x = pix & 511;
    float dy = (float)y - 256.f, dx = (float)x - 256.f;
    float dist = sqrtf(dy * dy + dx * dx);
    const float MAXR = 362.03867196751236f;
    int lo = 0, hi = 100;
    while (lo < hi) {
        int mid = (lo + hi) >> 1;
        float r = MAXR * (((float)(mid + 1)) * 0.01f);
        if (r <= dist) lo = mid + 1; else hi = mid;
    }
    outMask[idx] = (lo < 100) ? g_vset[b * 100 + lo] : 0.f;
}

// ---------------- inverse FFT rows: build D_a + i*D_b on the fly -------------
// pair p handles images a=2p, b=2p+1. Reads Z (g_nfq) + masks, writes g_cfq[p].
__global__ void __launch_bounds__(512)
inv_rows_kernel(const float* __restrict__ maskp) {
    __shared__ float2 sd[8][576];
    __shared__ float2 stw[512];
    int tid = threadIdx.x;
    stw[tid] = g_tw[tid];
    int p   = blockIdx.y;     // 0..11
    int r0  = blockIdx.x * 8;
    int ia = 2 * p, ib = 2 * p + 1;
    int ba = ia / 3, bb = ib / 3;
    int c  = tid;
    int mc = (512 - c) & 511;
    int xs = (c + 256) & 511;
#pragma unroll
    for (int row = 0; row < 8; row++) {
        int gr = r0 + row;
        int mr = (512 - gr) & 511;
        int ys = (gr + 256) & 511;
        size_t ofk = ((size_t)gr << 9) + c;
        size_t ofm = ((size_t)mr << 9) + mc;
        // image a
        float2 Zk = g_nfq[(size_t)ia * NPIX + ofk];
        float2 Zm = g_nfq[(size_t)ia * NPIX + ofm];
        float Nx = 0.5f*(Zk.x + Zm.x), Ny = 0.5f*(Zk.y - Zm.y);
        float Dx = 0.5f*(Zk.x - Zm.x), Dy = 0.5f*(Zk.y + Zm.y);
        float ma = maskp[(size_t)ba * NPIX + ((size_t)ys << 9) + xs];
        float Dax = ma * (Nx - Dy);
        float Day = ma * (Ny + Dx);
        // image b
        Zk = g_nfq[(size_t)ib * NPIX + ofk];
        Zm = g_nfq[(size_t)ib * NPIX + ofm];
        Nx = 0.5f*(Zk.x + Zm.x); Ny = 0.5f*(Zk.y - Zm.y);
        Dx = 0.5f*(Zk.x - Zm.x); Dy = 0.5f*(Zk.y + Zm.y);
        float mb = maskp[(size_t)bb * NPIX + ((size_t)ys << 9) + xs];
        float Dbx = mb * (Nx - Dy);
        float Dby = mb * (Ny + Dx);
        // packed = D_a + i*D_b
        sd[row][FPAD(drev(tid))] = make_float2(Dax - Dby, Day + Dbx);
    }
    __syncthreads();
    fft512_stages<1>(sd, stw);
#pragma unroll
    for (int row = 0; row < 8; row++)
        g_cfq[(size_t)p * NPIX + (size_t)(r0 + row) * 512 + tid] = sd[row][FPAD(tid)];
}

// ---------------- inverse FFT cols + hard/easy for both pair images ----------
__global__ void __launch_bounds__(512)
inv_cols_kernel(const float* __restrict__ clean, const float* __restrict__ noisy,
                float* __restrict__ hard, float* __restrict__ easy) {
    __shared__ float2 sd[8][576];
    __shared__ float2 stw[512];
    int tid = threadIdx.x;
    stw[tid] = g_tw[tid];
    int p   = blockIdx.y;     // 0..11
    int c0  = blockIdx.x * 8;
    float2* buf = g_cfq + (size_t)p * NPIX;
    int c = tid & 7;
#pragma unroll
    for (int it = 0; it < 8; it++) {
        int r = it * 64 + (tid >> 3);
        sd[c][FPAD(drev(r))] = buf[(size_t)r * 512 + c0 + c];
    }
    __syncthreads();
    fft512_stages<1>(sd, stw);
    const float scale = 1.f / 262144.f;
    int ia = 2 * p, ib = 2 * p + 1;
#pragma unroll
    for (int it = 0; it < 8; it++) {
        int r = it * 64 + (tid >> 3);
        float2 v = sd[c][FPAD(r)];
        float da = v.x * scale;
        float db = v.y * scale;
        size_t gia = (size_t)ia * NPIX + (size_t)r * 512 + c0 + c;
        size_t gib = (size_t)ib * NPIX + (size_t)r * 512 + c0 + c;
        hard[gia] = clean[gia] + da;
        easy[gia] = noisy[gia] - da;
        hard[gib] = clean[gib] + db;
        easy[gib] = noisy[gib] - db;
    }
}

// ---------------- launch ------------------------------------------------------
extern "C" void kernel_launch(void* const* d_in, const int* in_sizes, int n_in,
                              void* d_out, int out_size) {
    const float* clean = (const float*)d_in[0];
    const float* noisy = (const float*)d_in[1];
    const float* c1w = (const float*)d_in[2];
    const float* c1b = (const float*)d_in[3];
    const float* c2w = (const float*)d_in[4];
    const float* c2b = (const float*)d_in[5];
    const float* c3w = (const float*)d_in[6];
    const float* c3b = (const float*)d_in[7];
    const float* f1w = (const float*)d_in[8];
    const float* f1b = (const float*)d_in[9];
    const float* f2w = (const float*)d_in[10];
    const float* f2b = (const float*)d_in[11];

    float* hard  = (float*)d_out;
    float* easy  = hard + 6291456;
    float* maskp = easy + 6291456;

    float *p_fin, *p_p1, *p_p2, *p_y3;
    cudaGetSymbolAddress((void**)&p_fin, g_fin);
    cudaGetSymbolAddress((void**)&p_p1, g_p1);
    cudaGetSymbolAddress((void**)&p_p2, g_p2);
    cudaGetSymbolAddress((void**)&p_y3, g_y3);

    const int smem1 = (12 * 648 + 112 * 24 + 112) * 4;
    const int smem2 = (16 * 648 + 144 * 24 + 144) * 4;
    const int smem3 = (32 * 648 + 288 * 24 + 288) * 4;
    cudaFuncSetAttribute(convmma_kernel<12, 16, 512, 512, true, true>,
                         cudaFuncAttributeMaxDynamicSharedMemorySize, smem1);
    cudaFuncSetAttribute(convmma_kernel<16, 32, 256, 256, true, false>,
                         cudaFuncAttributeMaxDynamicSharedMemorySize, smem2);
    cudaFuncSetAttribute(convmma_kernel<32, 64, 128, 128, false, false>,
                         cudaFuncAttributeMaxDynamicSharedMemorySize, smem3);

    init_tw_kernel<<<1, 512>>>();

    fwd_rows_kernel<<<dim3(64, 24), 512>>>(noisy, clean);
    fwd_cols_kernel<<<dim3(64, 24), 512>>>();
    unpack_logmag_kernel<<<(NIMG * NPIX + 255) / 256, 256>>>();

    convmma_kernel<12, 16, 512, 512, true, true><<<dim3(16, 32, 8), 256, smem1>>>(
        nullptr, noisy, clean, p_fin, c1w, c1b, p_p1);
    convmma_kernel<16, 32, 256, 256, true, false><<<dim3(8, 16, 16), 256, smem2>>>(
        p_p1, nullptr, nullptr, nullptr, c2w, c2b, p_p2);
    convmma_kernel<32, 64, 128, 128, false, false><<<dim3(4, 8, 32), 256, smem3>>>(
        p_p2, nullptr, nullptr, nullptr, c3w, c3b, p_y3);

    reduce_mean_kernel<<<512, 256>>>(p_y3);
    fc1_kernel<<<8, 256>>>(f1w, f1b);
    head_kernel<<<dim3(100, 8), 128>>>(f2w, f2b);

    mask_kernel<<<(8 * NPIX + 255) / 256, 256>>>(maskp);
    inv_rows_kernel<<<dim3(64, 12), 512>>>(maskp);
    inv_cols_kernel<<<dim3(64, 12), 512>>>(clean, noisy, hard, easy);
}

// round 6
// speedup vs baseline: 2.4273x; 1.1536x over previous
#include <cuda_runtime.h>
#include <cuda_bf16.h>
#include <math.h>
#include <stdint.h>

#define NPIX 262144   // 512*512
#define NIMG 24       // 8 batch * 3 channels

// ---------------- scratch (device globals) -----------------------------------
static __device__ float2 g_nfq[NIMG * NPIX];     // packed spectrum Z = FFT(noisy + i*clean)
static __device__ float2 g_cfq[NIMG * NPIX];     // inverse-pass intermediate (12 pair images)
static __device__ float  g_fin[8 * 6 * NPIX];    // log-mag channels (B,6,512,512)
static __device__ float  g_p1 [8 * 16 * 65536];  // pooled conv1 out (256^2)
static __device__ float  g_p2 [8 * 32 * 16384];  // pooled conv2 out (128^2)
static __device__ float  g_y3 [8 * 64 * 16384];  // conv3 out (128^2)
static __device__ float  g_feat[8 * 64];
static __device__ float  g_h  [8 * 256];
static __device__ float  g_vset[8 * 100];
static __device__ float2 g_tw [512];             // W_512^k

// ---------------- twiddles ---------------------------------------------------
__global__ void init_tw_kernel() {
    int k = threadIdx.x;
    if (k < 512) {
        double s, c;
        sincospi(-(double)k / 256.0, &s, &c);
        g_tw[k] = make_float2((float)c, (float)s);
    }
}

// ---------------- complex helpers --------------------------------------------
__device__ __forceinline__ float2 cadd(float2 a, float2 b){ return make_float2(a.x+b.x, a.y+b.y); }
__device__ __forceinline__ float2 csub(float2 a, float2 b){ return make_float2(a.x-b.x, a.y-b.y); }
template<int INV>
__device__ __forceinline__ float2 ctw(float2 a, float2 w) {
    if (!INV) return make_float2(a.x*w.x - a.y*w.y, a.x*w.y + a.y*w.x);
    else      return make_float2(a.x*w.x + a.y*w.y, a.y*w.x - a.x*w.y);
}

// ---------------- 8-point DFT ------------------------------------------------
template<int INV>
__device__ __forceinline__ void dft8(float2* a) {
    const float C = 0.70710678118654752f;
    float2 b0 = cadd(a[0], a[4]), t4 = csub(a[0], a[4]);
    float2 b1 = cadd(a[1], a[5]), t5 = csub(a[1], a[5]);
    float2 b2 = cadd(a[2], a[6]), t6 = csub(a[2], a[6]);
    float2 b3 = cadd(a[3], a[7]), t7 = csub(a[3], a[7]);
    float2 b5, b6, b7;
    if (!INV) {
        b5 = make_float2(C*(t5.x + t5.y), C*(t5.y - t5.x));
        b6 = make_float2(t6.y, -t6.x);
        b7 = make_float2(C*(t7.y - t7.x), -C*(t7.x + t7.y));
    } else {
        b5 = make_float2(C*(t5.x - t5.y), C*(t5.y + t5.x));
        b6 = make_float2(-t6.y, t6.x);
        b7 = make_float2(-C*(t7.x + t7.y), C*(t7.x - t7.y));
    }
    float2 c0 = cadd(b0, b2), c2 = csub(b0, b2);
    float2 c1 = cadd(b1, b3), t3 = csub(b1, b3);
    float2 c4 = cadd(t4, b6), c6 = csub(t4, b6);
    float2 c5 = cadd(b5, b7), t7b = csub(b5, b7);
    float2 c3 = (!INV) ? make_float2(t3.y, -t3.x)  : make_float2(-t3.y, t3.x);
    float2 c7 = (!INV) ? make_float2(t7b.y, -t7b.x): make_float2(-t7b.y, t7b.x);
    a[0] = cadd(c0, c1); a[4] = csub(c0, c1);
    a[2] = cadd(c2, c3); a[6] = csub(c2, c3);
    a[1] = cadd(c4, c5); a[5] = csub(c4, c5);
    a[3] = cadd(c6, c7); a[7] = csub(c6, c7);
}

#define FPAD(p) ((p) + ((p) >> 3))
__device__ __forceinline__ int drev(int i) {
    return ((i & 7) << 6) | (i & 56) | (i >> 6);
}

template<int INV>
__device__ __forceinline__ void fft512_stages(float2 (*sd)[576], const float2* stw) {
    int tid = threadIdx.x;
    float2* s = sd[tid >> 6];
    int t = tid & 63;
    {
        float2 a[8];
#pragma unroll
        for (int j = 0; j < 8; j++) { int p = 8*t + j; a[j] = s[FPAD(p)]; }
        dft8<INV>(a);
#pragma unroll
        for (int m = 0; m < 8; m++) { int p = 8*t + m; s[FPAD(p)] = a[m]; }
    }
    __syncthreads();
    {
        int k = t & 7, base = ((t >> 3) << 6) + k;
        float2 a[8];
        a[0] = s[FPAD(base)];
#pragma unroll
        for (int j = 1; j < 8; j++) {
            int p = base + 8*j;
            a[j] = ctw<INV>(s[FPAD(p)], stw[8*j*k]);
        }
        dft8<INV>(a);
#pragma unroll
        for (int m = 0; m < 8; m++) { int p = base + 8*m; s[FPAD(p)] = a[m]; }
    }
    __syncthreads();
    {
        float2 a[8];
        a[0] = s[FPAD(t)];
#pragma unroll
        for (int j = 1; j < 8; j++) {
            int p = t + 64*j;
            a[j] = ctw<INV>(s[FPAD(p)], stw[j*t]);
        }
        dft8<INV>(a);
#pragma unroll
        for (int m = 0; m < 8; m++) { int p = t + 64*m; s[FPAD(p)] = a[m]; }
    }
    __syncthreads();
}

// ---------------- forward FFT rows: z = noisy + i*clean ----------------------
__global__ void __launch_bounds__(512)
fwd_rows_kernel(const float* __restrict__ noisy, const float* __restrict__ clean) {
    __shared__ float2 sd[8][576];
    __shared__ float2 stw[512];
    int tid = threadIdx.x;
    stw[tid] = g_tw[tid];
    int img = blockIdx.y;            // 0..23
    int r0  = blockIdx.x * 8;
    size_t base = (size_t)img * NPIX;
#pragma unroll
    for (int row = 0; row < 8; row++) {
        size_t gi = base + (size_t)(r0 + row) * 512 + tid;
        sd[row][FPAD(drev(tid))] = make_float2(noisy[gi], clean[gi]);
    }
    __syncthreads();
    fft512_stages<0>(sd, stw);
#pragma unroll
    for (int row = 0; row < 8; row++)
        g_nfq[base + (size_t)(r0 + row) * 512 + tid] = sd[row][FPAD(tid)];
}

// ---------------- forward FFT cols -------------------------------------------
__global__ void __launch_bounds__(512)
fwd_cols_kernel() {
    __shared__ float2 sd[8][576];
    __shared__ float2 stw[512];
    int tid = threadIdx.x;
    stw[tid] = g_tw[tid];
    int img = blockIdx.y;            // 0..23
    int c0  = blockIdx.x * 8;
    float2* buf = g_nfq + (size_t)img * NPIX;
    int c = tid & 7;
#pragma unroll
    for (int it = 0; it < 8; it++) {
        int r = it * 64 + (tid >> 3);
        sd[c][FPAD(drev(r))] = buf[(size_t)r * 512 + c0 + c];
    }
    __syncthreads();
    fft512_stages<0>(sd, stw);
#pragma unroll
    for (int it = 0; it < 8; it++) {
        int r = it * 64 + (tid >> 3);
        buf[(size_t)r * 512 + c0 + c] = sd[c][FPAD(r)];
    }
}

// ---------------- unpack Hermitian pair -> log-mag channels ------------------
// |N(-k)| == |N(k)| and |C(-k)| == |C(k)| (real images), so each work item
// handles a conjugate pair and writes both shifted positions. c in [0,256].
__global__ void unpack_logmag_kernel() {
    const int NC = 257;
    int idx = blockIdx.x * blockDim.x + threadIdx.x;
    if (idx >= NIMG * 512 * NC) return;
    int img = idx / (512 * NC);
    int rem = idx - img * (512 * NC);
    int r = rem / NC;
    int c = rem - r * NC;
    int mr = (512 - r) & 511, mc = (512 - c) & 511;
    float2 Zk = g_nfq[(size_t)img * NPIX + ((size_t)r << 9) + c];
    float2 Zm = g_nfq[(size_t)img * NPIX + ((size_t)mr << 9) + mc];
    float Nx = 0.5f * (Zk.x + Zm.x), Ny = 0.5f * (Zk.y - Zm.y);
    float Dx = 0.5f * (Zk.x - Zm.x), Dy = 0.5f * (Zk.y + Zm.y);
    float vN = log10f(sqrtf(Nx * Nx + Ny * Ny) + 1.f);
    float vC = log10f(sqrtf(Dx * Dx + Dy * Dy) + 1.f);
    int b = img / 3, ch = img - 3 * b;
    size_t o1 = ((size_t)((r + 256) & 511) << 9) + ((c + 256) & 511);
    size_t o2 = ((size_t)((mr + 256) & 511) << 9) + ((mc + 256) & 511);
    float* finN = g_fin + (size_t)(b * 6 + ch) * NPIX;
    float* finC = g_fin + (size_t)(b * 6 + 3 + ch) * NPIX;
    finN[o1] = vN; finN[o2] = vN;
    finC[o1] = vC; finC[o2] = vC;
}

// ---------------- bf16 MMA ---------------------------------------------------
#define MMA_BF16(d, a0,a1,a2,a3, b0,b1)                                        \
    asm("mma.sync.aligned.m16n8k16.row.col.f32.bf16.bf16.f32 "                 \
        "{%0,%1,%2,%3}, {%4,%5,%6,%7}, {%8,%9}, {%0,%1,%2,%3};"                \
        : "+f"(d[0]), "+f"(d[1]), "+f"(d[2]), "+f"(d[3])                       \
        : "r"(a0), "r"(a1), "r"(a2), "r"(a3), "r"(b0), "r"(b1))

// ---------------- implicit-GEMM 3x3 conv, bf16 m16n8k16 ----------------------
// block 256 thr, pixel tile 32x x 16y, 16 couts.
// K ordered channel-fastest: k = tap*CIN + ic -> (k,k+1) = adjacent channels =
// one aligned b32 (bf16x2) smem load. Channel stride CS=CIN+2 for bank spread.
template<int CIN, int COUT, int H, int W, bool POOL, bool GATHER>
__global__ void __launch_bounds__(256)
convmma_kernel(const float* __restrict__ in,
               const float* __restrict__ noisy, const float* __restrict__ clean,
               const float* __restrict__ fin,
               const float* __restrict__ wgt,
               const float* __restrict__ bias, float* __restrict__ out) {
    constexpr int K   = CIN * 9;
    constexpr int KP  = (K + 15) & ~15;
    constexpr int NPAIR = KP / 2;
    constexpr int CS  = CIN + 2;              // bf16 elems per pixel slot
    constexpr int SIN_ELEMS = 18 * 36 * CS;   // bf16
    constexpr int OGC = COUT / 16;

    extern __shared__ char smemc[];
    __nv_bfloat16* sIn = (__nv_bfloat16*)smemc;
    unsigned* wPk = (unsigned*)(smemc + ((SIN_ELEMS * 2 + 15) & ~15));
    int* lutp = (int*)(wPk + NPAIR * 20);

    int tid = threadIdx.x;
    int bz = blockIdx.z;
    int og = bz % OGC;
    int b  = bz / OGC;
    int x0 = blockIdx.x * 32, y0 = blockIdx.y * 16;

    // ---- lut of byte offsets per k-pair
    for (int p = tid; p < NPAIR; p += 256) {
        int k = 2 * p, v = 0;
        if (k < K) {
            int tap = k / CIN, ic = k - tap * CIN;
            v = ((tap / 3) * 36 + (tap % 3)) * CS * 2 + ic * 2;
        }
        lutp[p] = v;
    }
    // ---- weights packed as bf16x2 fragments
    for (int e = tid; e < NPAIR * 16; e += 256) {
        int p = e >> 4, o = e & 15;
        int k = 2 * p;
        float w0 = 0.f, w1 = 0.f;
        if (k < K) {
            int tap = k / CIN, ic = k - tap * CIN;
            int base = ((og * 16 + o) * CIN + ic) * 9 + tap;
            w0 = wgt[base];
            w1 = wgt[base + 9];
        }
        __nv_bfloat162 pr = __floats2bfloat162_rn(w0, w1);
        wPk[p * 20 + o] = *(unsigned*)&pr;
    }
    // ---- input tile (halo), bf16, channel-interleaved
    for (int e = tid; e < 18 * 36 * CIN; e += 256) {
        int ic = e / (18 * 36);
        int pix = e - ic * (18 * 36);
        int r = pix / 36, cc = pix - r * 36;
        int gy = y0 + r - 1, gx = x0 + cc - 1;
        float v = 0.f;
        if (cc < 34 && (unsigned)gy < (unsigned)H && (unsigned)gx < (unsigned)W) {
            if (GATHER) {
                int grp = ic / 3, sub = ic - 3 * grp;
                const float* src =
                    (grp == 0) ? noisy + (size_t)(b * 3 + sub) * NPIX :
                    (grp == 1) ? fin   + (size_t)(b * 6 + sub) * NPIX :
                    (grp == 2) ? clean + (size_t)(b * 3 + sub) * NPIX :
                                 fin   + (size_t)(b * 6 + 3 + sub) * NPIX;
                v = src[((size_t)gy << 9) + gx];
            } else {
                v = in[((size_t)(b * CIN + ic) * H + gy) * W + gx];
            }
        }
        sIn[pix * CS + ic] = __float2bfloat16_rn(v);
    }
    __syncthreads();

    int lane = tid & 31, w = tid >> 5;
    int gid = lane >> 2, tig = lane & 3;

    float acc[4][2][4];
#pragma unroll
    for (int mt = 0; mt < 4; mt++)
#pragma unroll
        for (int nt = 0; nt < 2; nt++)
#pragma unroll
            for (int c = 0; c < 4; c++) acc[mt][nt][c] = 0.f;

    int Abase[4];
#pragma unroll
    for (int mt = 0; mt < 4; mt++)
        Abase[mt] = (((2 * w + (mt & 1)) * 36 + (mt >> 1) * 16 + gid) * CS) * 2;

    const char* sInB = (const char*)sIn;

#pragma unroll 3
    for (int kc = 0; kc < KP / 16; kc++) {
        int pb = kc * 8;
        int lp0 = lutp[pb + tig];
        int lp1 = lutp[pb + tig + 4];
        unsigned b0[2], b1[2];
#pragma unroll
        for (int nt = 0; nt < 2; nt++) {
            b0[nt] = wPk[(pb + tig) * 20 + nt * 8 + gid];
            b1[nt] = wPk[(pb + tig + 4) * 20 + nt * 8 + gid];
        }
#pragma unroll
        for (int mt = 0; mt < 4; mt++) {
            const char* pA = sInB + Abase[mt];
            unsigned a0 = *(const unsigned*)(pA + lp0);
            unsigned a1 = *(const unsigned*)(pA + lp0 + 8 * CS * 2);
            unsigned a2 = *(const unsigned*)(pA + lp1);
            unsigned a3 = *(const unsigned*)(pA + lp1 + 8 * CS * 2);
#pragma unroll
            for (int nt = 0; nt < 2; nt++)
                MMA_BF16(acc[mt][nt], a0, a1, a2, a3, b0[nt], b1[nt]);
        }
    }

    if (POOL) {
        const int Ho = H / 2, Wo = W / 2;
        int oy = (y0 >> 1) + w;
#pragma unroll
        for (int half = 0; half < 2; half++) {
#pragma unroll
            for (int nt = 0; nt < 2; nt++)
#pragma unroll
                for (int c = 0; c < 2; c++) {
                    int o = og * 16 + nt * 8 + 2 * tig + c;
                    float bv = bias[o];
                    float sa = fmaxf(acc[half*2][nt][c]   + bv, 0.f) +
                               fmaxf(acc[half*2+1][nt][c] + bv, 0.f);
                    float sb = fmaxf(acc[half*2][nt][c+2]   + bv, 0.f) +
                               fmaxf(acc[half*2+1][nt][c+2] + bv, 0.f);
                    sa += __shfl_xor_sync(0xffffffffu, sa, 4);
                    sb += __shfl_xor_sync(0xffffffffu, sb, 4);
                    if (!(gid & 1)) {
                        int oxa = (x0 + half * 16 + gid) >> 1;
                        size_t base = ((size_t)(b * COUT + o) * Ho + oy) * Wo;
                        out[base + oxa]     = 0.25f * sa;
                        out[base + oxa + 4] = 0.25f * sb;
                    }
                }
        }
    } else {
#pragma unroll
        for (int mt = 0; mt < 4; mt++) {
            int Y = y0 + 2 * w + (mt & 1);
            int X = x0 + (mt >> 1) * 16 + gid;
#pragma unroll
            for (int nt = 0; nt < 2; nt++)
#pragma unroll
                for (int c = 0; c < 2; c++) {
                    int o = og * 16 + nt * 8 + 2 * tig + c;
                    float bv = bias[o];
                    size_t base = ((size_t)(b * COUT + o) * H + Y) * W + X;
                    out[base]     = fmaxf(acc[mt][nt][c]   + bv, 0.f);
                    out[base + 8] = fmaxf(acc[mt][nt][c+2] + bv, 0.f);
                }
        }
    }
}

// ---------------- global mean over 128x128 -----------------------------------
__global__ void __launch_bounds__(256)
reduce_mean_kernel(const float* __restrict__ y3) {
    __shared__ float red[256];
    int bc = blockIdx.x;
    int t  = threadIdx.x;
    const float* p = y3 + (size_t)bc * 16384;
    float s = 0.f;
    for (int i = t; i < 16384; i += 256) s += p[i];
    red[t] = s;
    __syncthreads();
    for (int off = 128; off; off >>= 1) {
        if (t < off) red[t] += red[t + off];
        __syncthreads();
    }
    if (t == 0) g_feat[bc] = red[0] * (1.f / 16384.f);
}

// ---------------- fc1 --------------------------------------------------------
__global__ void __launch_bounds__(256)
fc1_kernel(const float* __restrict__ w, const float* __restrict__ bias) {
    __shared__ float sf[64];
    int b = blockIdx.x, t = threadIdx.x;
    if (t < 64) sf[t] = g_feat[b * 64 + t];
    __syncthreads();
    float s = 0.f;
    const float* wr = w + (size_t)t * 64;
#pragma unroll
    for (int i = 0; i < 64; i++) s = fmaf(wr[i], sf[i], s);
    g_h[b * 256 + t] = s + bias[t];
}

// ---------------- head -------------------------------------------------------
__global__ void __launch_bounds__(128)
head_kernel(const float* __restrict__ w, const float* __restrict__ bias) {
    __shared__ float sh[256];
    __shared__ float red[128];
    int j = blockIdx.x;
    int b = blockIdx.y;
    int t = threadIdx.x;
    for (int i = t; i < 256; i += 128) sh[i] = g_h[b * 256 + i];
    __syncthreads();
    float z = -3.4e38f;
    if (t < 100) {
        const float* wr = w + (size_t)(j * 100 + t) * 256;
        float s = 0.f;
        for (int i = 0; i < 256; i++) s = fmaf(wr[i], sh[i], s);
        z = (s + bias[j * 100 + t]) * 0.1f;
    }
    red[t] = z;
    __syncthreads();
    for (int off = 64; off; off >>= 1) {
        if (t < off) red[t] = fmaxf(red[t], red[t + off]);
        __syncthreads();
    }
    float m = red[0];
    __syncthreads();
    float p = (t < 100) ? expf(z - m) : 0.f;
    red[t] = p;
    __syncthreads();
    for (int off = 64; off; off >>= 1) {
        if (t < off) red[t] += red[t + off];
        __syncthreads();
    }
    float S = red[0];
    __syncthreads();
    float rf = ((float)t + 1.0f) * 0.01f;
    red[t] = p * rf;
    __syncthreads();
    for (int off = 64; off; off >>= 1) {
        if (t < off) red[t] += red[t + off];
        __syncthreads();
    }
    if (t == 0) g_vset[b * 100 + j] = red[0] / S;
}

// ---------------- radial mask ------------------------------------------------
__global__ void mask_kernel(float* __restrict__ outMask) {
    int idx = blockIdx.x * blockDim.x + threadIdx.x;
    if (idx >= 8 * NPIX) return;
    int b = idx >> 18;
    int pix = idx & (NPIX - 1);
    int y = pix >> 9, x = pix & 511;
    float dy = (float)y - 256.f, dx = (float)x - 256.f;
    float dist = sqrtf(dy * dy + dx * dx);
    const float MAXR = 362.03867196751236f;
    int lo = 0, hi = 100;
    while (lo < hi) {
        int mid = (lo + hi) >> 1;
        float r = MAXR * (((float)(mid + 1)) * 0.01f);
        if (r <= dist) lo = mid + 1; else hi = mid;
    }
    outMask[idx] = (lo < 100) ? g_vset[b * 100 + lo] : 0.f;
}

// ---------------- inverse FFT rows: build D_a + i*D_b on the fly -------------
__global__ void __launch_bounds__(512)
inv_rows_kernel(const float* __restrict__ maskp) {
    __shared__ float2 sd[8][576];
    __shared__ float2 stw[512];
    int tid = threadIdx.x;
    stw[tid] = g_tw[tid];
    int p   = blockIdx.y;     // 0..11
    int r0  = blockIdx.x * 8;
    int ia = 2 * p, ib = 2 * p + 1;
    int ba = ia / 3, bb = ib / 3;
    int c  = tid;
    int mc = (512 - c) & 511;
    int xs = (c + 256) & 511;
#pragma unroll
    for (int row = 0; row < 8; row++) {
        int gr = r0 + row;
        int mr = (512 - gr) & 511;
        int ys = (gr + 256) & 511;
        size_t ofk = ((size_t)gr << 9) + c;
        size_t ofm = ((size_t)mr << 9) + mc;
        float2 Zk = g_nfq[(size_t)ia * NPIX + ofk];
        float2 Zm = g_nfq[(size_t)ia * NPIX + ofm];
        float Nx = 0.5f*(Zk.x + Zm.x), Ny = 0.5f*(Zk.y - Zm.y);
        float Dx = 0.5f*(Zk.x - Zm.x), Dy = 0.5f*(Zk.y + Zm.y);
        float ma = maskp[(size_t)ba * NPIX + ((size_t)ys << 9) + xs];
        float Dax = ma * (Nx - Dy);
        float Day = ma * (Ny + Dx);
        Zk = g_nfq[(size_t)ib * NPIX + ofk];
        Zm = g_nfq[(size_t)ib * NPIX + ofm];
        Nx = 0.5f*(Zk.x + Zm.x); Ny = 0.5f*(Zk.y - Zm.y);
        Dx = 0.5f*(Zk.x - Zm.x); Dy = 0.5f*(Zk.y + Zm.y);
        float mb = maskp[(size_t)bb * NPIX + ((size_t)ys << 9) + xs];
        float Dbx = mb * (Nx - Dy);
        float Dby = mb * (Ny + Dx);
        sd[row][FPAD(drev(tid))] = make_float2(Dax - Dby, Day + Dbx);
    }
    __syncthreads();
    fft512_stages<1>(sd, stw);
#pragma unroll
    for (int row = 0; row < 8; row++)
        g_cfq[(size_t)p * NPIX + (size_t)(r0 + row) * 512 + tid] = sd[row][FPAD(tid)];
}

// ---------------- inverse FFT cols + hard/easy for both pair images ----------
__global__ void __launch_bounds__(512)
inv_cols_kernel(const float* __restrict__ clean, const float* __restrict__ noisy,
                float* __restrict__ hard, float* __restrict__ easy) {
    __shared__ float2 sd[8][576];
    __shared__ float2 stw[512];
    int tid = threadIdx.x;
    stw[tid] = g_tw[tid];
    int p   = blockIdx.y;     // 0..11
    int c0  = blockIdx.x * 8;
    float2* buf = g_cfq + (size_t)p * NPIX;
    int c = tid & 7;
#pragma unroll
    for (int it = 0; it < 8; it++) {
        int r = it * 64 + (tid >> 3);
        sd[c][FPAD(drev(r))] = buf[(size_t)r * 512 + c0 + c];
    }
    __syncthreads();
    fft512_stages<1>(sd, stw);
    const float scale = 1.f / 262144.f;
    int ia = 2 * p, ib = 2 * p + 1;
#pragma unroll
    for (int it = 0; it < 8; it++) {
        int r = it * 64 + (tid >> 3);
        float2 v = sd[c][FPAD(r)];
        float da = v.x * scale;
        float db = v.y * scale;
        size_t gia = (size_t)ia * NPIX + (size_t)r * 512 + c0 + c;
        size_t gib = (size_t)ib * NPIX + (size_t)r * 512 + c0 + c;
        hard[gia] = clean[gia] + da;
        easy[gia] = noisy[gia] - da;
        hard[gib] = clean[gib] + db;
        easy[gib] = noisy[gib] - db;
    }
}

// ---------------- launch ------------------------------------------------------
extern "C" void kernel_launch(void* const* d_in, const int* in_sizes, int n_in,
                              void* d_out, int out_size) {
    const float* clean = (const float*)d_in[0];
    const float* noisy = (const float*)d_in[1];
    const float* c1w = (const float*)d_in[2];
    const float* c1b = (const float*)d_in[3];
    const float* c2w = (const float*)d_in[4];
    const float* c2b = (const float*)d_in[5];
    const float* c3w = (const float*)d_in[6];
    const float* c3b = (const float*)d_in[7];
    const float* f1w = (const float*)d_in[8];
    const float* f1b = (const float*)d_in[9];
    const float* f2w = (const float*)d_in[10];
    const float* f2b = (const float*)d_in[11];

    float* hard  = (float*)d_out;
    float* easy  = hard + 6291456;
    float* maskp = easy + 6291456;

    float *p_fin, *p_p1, *p_p2, *p_y3;
    cudaGetSymbolAddress((void**)&p_fin, g_fin);
    cudaGetSymbolAddress((void**)&p_p1, g_p1);
    cudaGetSymbolAddress((void**)&p_p2, g_p2);
    cudaGetSymbolAddress((void**)&p_y3, g_y3);

    // smem bytes: align(sIn) + wPk(NPAIR*20*4) + lutp(NPAIR*4)
    const int smem1 = ((18*36*14*2 + 15) & ~15) + 56 * 20 * 4 + 56 * 4;
    const int smem2 = ((18*36*18*2 + 15) & ~15) + 72 * 20 * 4 + 72 * 4;
    const int smem3 = ((18*36*34*2 + 15) & ~15) + 144 * 20 * 4 + 144 * 4;
    cudaFuncSetAttribute(convmma_kernel<12, 16, 512, 512, true, true>,
                         cudaFuncAttributeMaxDynamicSharedMemorySize, smem1);
    cudaFuncSetAttribute(convmma_kernel<16, 32, 256, 256, true, false>,
                         cudaFuncAttributeMaxDynamicSharedMemorySize, smem2);
    cudaFuncSetAttribute(convmma_kernel<32, 64, 128, 128, false, false>,
                         cudaFuncAttributeMaxDynamicSharedMemorySize, smem3);

    init_tw_kernel<<<1, 512>>>();

    fwd_rows_kernel<<<dim3(64, 24), 512>>>(noisy, clean);
    fwd_cols_kernel<<<dim3(64, 24), 512>>>();
    unpack_logmag_kernel<<<(NIMG * 512 * 257 + 255) / 256, 256>>>();

    convmma_kernel<12, 16, 512, 512, true, true><<<dim3(16, 32, 8), 256, smem1>>>(
        nullptr, noisy, clean, p_fin, c1w, c1b, p_p1);
    convmma_kernel<16, 32, 256, 256, true, false><<<dim3(8, 16, 16), 256, smem2>>>(
        p_p1, nullptr, nullptr, nullptr, c2w, c2b, p_p2);
    convmma_kernel<32, 64, 128, 128, false, false><<<dim3(4, 8, 32), 256, smem3>>>(
        p_p2, nullptr, nullptr, nullptr, c3w, c3b, p_y3);

    reduce_mean_kernel<<<512, 256>>>(p_y3);
    fc1_kernel<<<8, 256>>>(f1w, f1b);
    head_kernel<<<dim3(100, 8), 128>>>(f2w, f2b);

    mask_kernel<<<(8 * NPIX + 255) / 256, 256>>>(maskp);
    inv_rows_kernel<<<dim3(64, 12), 512>>>(maskp);
    inv_cols_kernel<<<dim3(64, 12), 512>>>(clean, noisy, hard, easy);
}